// round 11
// baseline (speedup 1.0000x reference)
#include <cuda_runtime.h>
#include <cuda_fp16.h>
#include <mma.h>
#include <cstdint>

// ---------------------------------------------------------------------------
// SMPL fused pipeline, round 11 (R10 with alignment fix):
//  - single build mega-kernel (E + G + JT), JT in fp32 from raw inputs
//  - pose rows: scalar loads (row pitch 20670 floats is NOT 16B-aligned!)
//  - high-occupancy reduce (456x4 blocks), zero-init pads
//  - GEMM1 fp16 single-term (256x128, 512 thr, split-K 12)
//  - GEMM2 single-term fp16
//  - 6 launches total
// ---------------------------------------------------------------------------

namespace smpl {

constexpr int V    = 6890;
constexpr int NB   = 10;
constexpr int NJ   = 24;
constexpr int NK   = 19;
constexpr int B    = 1024;

constexpr int VP   = 6912;
constexpr int M1   = 512;
constexpr int N1   = 768;
constexpr int SPLITK1 = 12;           // KSEG = 576
constexpr int KSEG = VP / SPLITK1;
constexpr int KQ   = 256;             // 218 padded
constexpr int N2   = 1408;            // 1368 padded

// GEMM1 fp16 operands (K = v contiguous). Pad regions rely on zero-init.
__device__ __align__(256) __half g_Gh16[M1 * VP];
__device__ __align__(256) __half g_Eh16[N1 * VP];

// GEMM2 operands, K(=q) contiguous. Pads zero-init.
__device__ __align__(256) __half g_A2h[B * KQ];
__device__ __align__(256) __half g_CTt[N2 * KQ];

__device__ __align__(256) float g_Cp [SPLITK1 * M1 * N1];
__device__ __align__(256) float g_S  [456];
__device__ __align__(256) float g_JT [24 * 33];
__device__ __align__(256) float g_Rg [B * 288];
__device__ __align__(256) float g_P  [B * N2];

__constant__ int c_par[24] = {-1,0,0,0,1,2,3,4,5,6,7,8,9,9,9,12,13,14,16,17,18,19,20,21};

// ---------------------------------------------------------------------------
// k_build: one launch builds Eh (241*9 blocks), Gh (36 blocks), JT (33 blocks)
// ---------------------------------------------------------------------------
constexpr int EB = 241 * 9;           // 2169

__global__ void __launch_bounds__(192) k_build(
        const float* __restrict__ posedirs,
        const float* __restrict__ shapedirs,
        const float* __restrict__ v_template,
        const float* __restrict__ joint_reg,
        const float* __restrict__ weights,
        const float* __restrict__ J_reg) {
    __shared__ float red[24][193];
    const int b   = blockIdx.x;
    const int tid = threadIdx.x;

    if (b < EB) {
        const int y  = b / 9;
        const int xb = b - 9 * y;
        const int vv = (xb * 192 + tid) * 4;
        if (y < 207) {
            const int p = y;
            const float* src = posedirs + (size_t)p * (V * 3);
            float f[12];
#pragma unroll
            for (int u = 0; u < 4; ++u)
#pragma unroll
                for (int c = 0; c < 3; ++c)
                    f[3 * u + c] = (vv + u < V) ? src[3 * (vv + u) + c] : 0.f;
#pragma unroll
            for (int c = 0; c < 3; ++c) {
                __half* dst = g_Eh16 + (size_t)(3 * p + c) * VP + vv;
                *(__half2*)dst       = __floats2half2_rn(f[c], f[3 + c]);
                *(__half2*)(dst + 2) = __floats2half2_rn(f[6 + c], f[9 + c]);
            }
        } else {
            const int n = 621 + (y - 207);     // 621..654
            float f[4] = {0.f, 0.f, 0.f, 0.f};
            if (n < 651) {
                int t = n - 621, q = t / 3, c = t - 3 * q;
                const float* src = shapedirs + (size_t)q * (V * 3);
#pragma unroll
                for (int u = 0; u < 4; ++u)
                    if (vv + u < V) f[u] = src[3 * (vv + u) + c];
            } else if (n < 654) {
                int c = n - 651;
#pragma unroll
                for (int u = 0; u < 4; ++u)
                    if (vv + u < V) f[u] = v_template[3 * (vv + u) + c];
            } else {
#pragma unroll
                for (int u = 0; u < 4; ++u)
                    if (vv + u < V) f[u] = 1.f;
            }
            __half* dst = g_Eh16 + (size_t)n * VP + vv;
            *(__half2*)dst       = __floats2half2_rn(f[0], f[1]);
            *(__half2*)(dst + 2) = __floats2half2_rn(f[2], f[3]);
        }
    } else if (b < EB + 36) {
        const int v = (b - EB) * 192 + tid;
        const bool ok = v < V;
        float jr[NK], w[NJ];
#pragma unroll
        for (int c = 0; c < NK; ++c)
            jr[c] = ok ? joint_reg[(size_t)v * NK + c] : 0.f;
#pragma unroll
        for (int c = 0; c < NJ; ++c)
            w[c] = ok ? weights[(size_t)v * NJ + c] : 0.f;
        __half* dst = g_Gh16 + v;
        for (int k = 0; k < NK; ++k) {
            float a = jr[k];
#pragma unroll
            for (int j = 0; j < NJ; ++j)
                dst[(size_t)(k * NJ + j) * VP] = __float2half_rn(a * w[j]);
        }
        // rows 456..511: G tail = J_reg columns (used only via zero E pad?
        // No — Jreg rows ARE needed; they feed nothing anymore since JT is
        // computed directly. Rows 456..511 stay zero (zero-init).)
    } else {
        const int t = b - EB - 36;             // 0..32
        float acc[NJ];
#pragma unroll
        for (int j = 0; j < NJ; ++j) acc[j] = 0.f;
        for (int v = tid; v < V; v += 192) {
            float ev;
            if (t < 30) {
                int q = t / 3, c = t - 3 * q;
                ev = shapedirs[(size_t)q * (V * 3) + 3 * v + c];
            } else {
                ev = v_template[3 * v + (t - 30)];
            }
            const float* jrow = J_reg + (size_t)v * NJ;
#pragma unroll
            for (int j = 0; j < NJ; ++j) acc[j] += jrow[j] * ev;
        }
#pragma unroll
        for (int j = 0; j < NJ; ++j) red[j][tid] = acc[j];
        __syncthreads();
        if (tid < NJ) {
            float s = 0.f;
#pragma unroll 8
            for (int i = 0; i < 192; ++i) s += red[tid][i];
            g_JT[tid * 33 + t] = s;
        }
    }
}

// ---------------------------------------------------------------------------
// GEMM1: C[m][n] = sum_v Gh[m,v]*Eh[n,v], fp16 single term (proven R9).
// CTA 256x128, BK=32, 512 threads = 16 warps as 8m x 2n.
// ---------------------------------------------------------------------------
constexpr int G1A    = 256 * 40;
constexpr int G1B    = 128 * 40;
constexpr int G1_BUF = G1A + G1B;
constexpr int G1_SMEM = 2 * G1_BUF * 2;        // 61440 bytes

__global__ void __launch_bounds__(512, 1) k_gemm1_wmma() {
    using namespace nvcuda;
    extern __shared__ __align__(16) __half dynsmem[];

    const int n0    = blockIdx.x * 128;
    const int m0    = blockIdx.y * 256;
    const int split = blockIdx.z;
    const int tid   = threadIdx.x;
    const int wid   = tid >> 5;
    const int wm    = (wid & 7) * 32;
    const int wn    = (wid >> 3) * 64;

    wmma::fragment<wmma::accumulator, 16, 16, 16, float> acc[2][4];
#pragma unroll
    for (int i = 0; i < 2; ++i)
#pragma unroll
        for (int j = 0; j < 4; ++j)
            wmma::fill_fragment(acc[i][j], 0.f);

    const int kbase = split * KSEG;
    const int nIter = KSEG / 32;               // 18

    const int rA0 = tid >> 2;
    const int cA  = (tid & 3) * 8;

    uint4 pA[2], pB;

    auto ldg_tile = [&](int kk) {
#pragma unroll
        for (int i = 0; i < 2; ++i) {
            int row = rA0 + 128 * i;
            pA[i] = *(const uint4*)(g_Gh16 + (size_t)(m0 + row) * VP + kk + cA);
        }
        pB = *(const uint4*)(g_Eh16 + (size_t)(n0 + rA0) * VP + kk + cA);
    };
    auto sts_tile = [&](int buf) {
        __half* base = dynsmem + buf * G1_BUF;
#pragma unroll
        for (int i = 0; i < 2; ++i) {
            int row = rA0 + 128 * i;
            *(uint4*)(base + row * 40 + cA) = pA[i];
        }
        *(uint4*)(base + G1A + rA0 * 40 + cA) = pB;
    };

    ldg_tile(kbase);
    sts_tile(0);
    ldg_tile(kbase + 32);
    __syncthreads();

    for (int it = 0; it < nIter; ++it) {
        const int cur = it & 1;
        if (it + 1 < nIter) sts_tile(1 - cur);
        if (it + 2 < nIter) ldg_tile(kbase + (it + 2) * 32);

        const __half* Ah = dynsmem + cur * G1_BUF;
        const __half* Bh = Ah + G1A;
#pragma unroll
        for (int k0 = 0; k0 < 32; k0 += 16) {
            wmma::fragment<wmma::matrix_a, 16, 16, 16, __half,
                           wmma::row_major> ah[2];
            wmma::fragment<wmma::matrix_b, 16, 16, 16, __half,
                           wmma::col_major> bh[4];
#pragma unroll
            for (int i = 0; i < 2; ++i)
                wmma::load_matrix_sync(ah[i], Ah + (wm + i * 16) * 40 + k0, 40);
#pragma unroll
            for (int j = 0; j < 4; ++j)
                wmma::load_matrix_sync(bh[j], Bh + (wn + j * 16) * 40 + k0, 40);
#pragma unroll
            for (int i = 0; i < 2; ++i)
#pragma unroll
                for (int j = 0; j < 4; ++j)
                    wmma::mma_sync(acc[i][j], ah[i], bh[j], acc[i][j]);
        }
        __syncthreads();
    }

    float* Co = g_Cp + (size_t)split * (M1 * N1);
#pragma unroll
    for (int i = 0; i < 2; ++i)
#pragma unroll
        for (int j = 0; j < 4; ++j)
            wmma::store_matrix_sync(
                &Co[(size_t)(m0 + wm + i * 16) * N1 + n0 + wn + j * 16],
                acc[i][j], N1, wmma::mem_row_major);
}

// ---------------------------------------------------------------------------
// Reduce: 456 kj-rows x 4 col-chunks of 164; sums 12 planes, writes CTt fp16
// (scatter by q,c) + S. Pads are zero-initialized globals, never touched.
// ---------------------------------------------------------------------------
__global__ void __launch_bounds__(128) k_reduce() {
    const int blk   = blockIdx.x;
    const int kj    = blk >> 2;
    const int chunk = blk & 3;
    const int base  = chunk * 164;

    for (int i = threadIdx.x; i < 164; i += 128) {
        int col = base + i;
        if (col > 654) break;
        float val = 0.f;
        size_t off = (size_t)kj * N1 + col;
#pragma unroll
        for (int sp = 0; sp < SPLITK1; ++sp)
            val += g_Cp[(size_t)sp * (M1 * N1) + off];
        if (col == 654) {
            g_S[kj] = val;
        } else {
            int q, c;
            if (col < 621)      { q = 11 + col / 3; c = col - 3 * (col / 3); }
            else if (col < 651) { int t = col - 621; q = 1 + t / 3; c = t - 3 * (t / 3); }
            else                { q = 0; c = col - 651; }
            g_CTt[(size_t)(3 * kj + c) * KQ + q] = __float2half_rn(val);
        }
    }
}

// ---------------------------------------------------------------------------
// Per-body prep (one warp / body). Emits A2 row [b][q] as single fp16.
// ---------------------------------------------------------------------------
__global__ void k_prep(const float* __restrict__ beta,
                       const float* __restrict__ theta) {
    const int b = blockIdx.x;
    const int lane = threadIdx.x;

    __shared__ float Rsm[24][9];
    __shared__ float Jm[24][3];
    __shared__ float Ag[24][12];
    __shared__ float bet[10];

    if (lane < 10) bet[lane] = beta[b * NB + lane];
    __syncwarp();

    if (lane < 24) {
        float tx = theta[b * 72 + lane * 3 + 0];
        float ty = theta[b * 72 + lane * 3 + 1];
        float tz = theta[b * 72 + lane * 3 + 2];
        float ax = tx + 1e-8f, ay = ty + 1e-8f, az = tz + 1e-8f;
        float angle = sqrtf(ax * ax + ay * ay + az * az);
        float half = 0.5f * angle;
        float s = sinf(half), cw = cosf(half);
        float vx = tx / angle * s, vy = ty / angle * s, vz = tz / angle * s;
        float qn = sqrtf(cw * cw + vx * vx + vy * vy + vz * vz);
        float w = cw / qn, x = vx / qn, y = vy / qn, z = vz / qn;
        Rsm[lane][0] = 1.f - 2.f * (y * y + z * z);
        Rsm[lane][1] = 2.f * (x * y - w * z);
        Rsm[lane][2] = 2.f * (x * z + w * y);
        Rsm[lane][3] = 2.f * (x * y + w * z);
        Rsm[lane][4] = 1.f - 2.f * (x * x + z * z);
        Rsm[lane][5] = 2.f * (y * z - w * x);
        Rsm[lane][6] = 2.f * (x * z - w * y);
        Rsm[lane][7] = 2.f * (y * z + w * x);
        Rsm[lane][8] = 1.f - 2.f * (x * x + y * y);
#pragma unroll
        for (int c = 0; c < 3; ++c) {
            float val = g_JT[lane * 33 + 30 + c];
#pragma unroll
            for (int n = 0; n < 10; ++n)
                val += bet[n] * g_JT[lane * 33 + n * 3 + c];
            Jm[lane][c] = val;
        }
    }
    __syncwarp();

    for (int q = lane; q < 218; q += 32) {
        float val;
        if (q == 0) val = 1.f;
        else if (q <= 10) val = bet[q - 1];
        else {
            int p = q - 11;
            int i = p / 9 + 1, e = p - 9 * (p / 9);
            val = Rsm[i][e] - ((e == 0 || e == 4 || e == 8) ? 1.f : 0.f);
        }
        g_A2h[(size_t)b * KQ + q] = __float2half_rn(val);
    }

    const int r = lane >> 2, cc = lane & 3;
    for (int i = 0; i < 24; ++i) {
        if (lane < 12) {
            float val;
            if (i == 0) {
                val = (cc < 3) ? Rsm[0][r * 3 + cc] * (cc == 0 ? 1.f : -1.f)
                               : Jm[0][r];
            } else {
                int par = c_par[i];
                float l0, l1, l2;
                if (cc < 3) {
                    l0 = Rsm[i][0 * 3 + cc];
                    l1 = Rsm[i][1 * 3 + cc];
                    l2 = Rsm[i][2 * 3 + cc];
                } else {
                    l0 = Jm[i][0] - Jm[par][0];
                    l1 = Jm[i][1] - Jm[par][1];
                    l2 = Jm[i][2] - Jm[par][2];
                }
                val = Ag[par][r * 4 + 0] * l0 + Ag[par][r * 4 + 1] * l1 +
                      Ag[par][r * 4 + 2] * l2;
                if (cc == 3) val += Ag[par][r * 4 + 3];
            }
            Ag[i][r * 4 + cc] = val;
        }
        __syncwarp();
    }

    for (int idx = lane; idx < 288; idx += 32) {
        int j = idx / 12, e = idx - 12 * j;
        float out;
        if (e < 9) {
            int rr = e / 3, c = e - 3 * rr;
            out = Ag[j][rr * 4 + c];
        } else {
            int rr = e - 9;
            out = Ag[j][rr * 4 + 3] -
                  (Ag[j][rr * 4 + 0] * Jm[j][0] + Ag[j][rr * 4 + 1] * Jm[j][1] +
                   Ag[j][rr * 4 + 2] * Jm[j][2]);
        }
        g_Rg[b * 288 + idx] = out;
    }
}

// ---------------------------------------------------------------------------
// GEMM2: P[b][m] = sum_q A2h[b,q]*CTt[m,q], single-term fp16.
// CTA 128x128, BK=32, 8 warps as 4b x 2m.
// ---------------------------------------------------------------------------
__global__ void __launch_bounds__(256, 2) k_gemm2_wmma() {
    using namespace nvcuda;

    __shared__ __align__(16) __half Ash[128][40];
    __shared__ __align__(16) __half Bs [128][40];

    const int n0  = blockIdx.x * 128;
    const int b0  = blockIdx.y * 128;
    const int tid = threadIdx.x;
    const int wid = tid >> 5;
    const int wb  = (wid & 3) * 32;
    const int wn  = (wid >> 2) * 64;

    wmma::fragment<wmma::accumulator, 16, 16, 16, float> acc[2][4];
#pragma unroll
    for (int i = 0; i < 2; ++i)
#pragma unroll
        for (int j = 0; j < 4; ++j)
            wmma::fill_fragment(acc[i][j], 0.f);

    const int nIter = KQ / 32;                 // 8

    uint4 pA[2], pB[2];
    auto ldg_tile = [&](int kk) {
#pragma unroll
        for (int i = 0; i < 2; ++i) {
            int linear = tid + 256 * i;
            int row = linear >> 2, c = (linear & 3) * 8;
            pA[i] = *(const uint4*)(g_A2h + (size_t)(b0 + row) * KQ + kk + c);
            pB[i] = *(const uint4*)(g_CTt + (size_t)(n0 + row) * KQ + kk + c);
        }
    };

    ldg_tile(0);

    for (int it = 0; it < nIter; ++it) {
        __syncthreads();
#pragma unroll
        for (int i = 0; i < 2; ++i) {
            int linear = tid + 256 * i;
            int row = linear >> 2, c = (linear & 3) * 8;
            *(uint4*)&Ash[row][c] = pA[i];
            *(uint4*)&Bs[row][c]  = pB[i];
        }
        __syncthreads();
        if (it + 1 < nIter) ldg_tile((it + 1) * 32);

#pragma unroll
        for (int k0 = 0; k0 < 32; k0 += 16) {
            wmma::fragment<wmma::matrix_a, 16, 16, 16, __half,
                           wmma::row_major> ah[2];
            wmma::fragment<wmma::matrix_b, 16, 16, 16, __half,
                           wmma::col_major> bh[4];
#pragma unroll
            for (int i = 0; i < 2; ++i)
                wmma::load_matrix_sync(ah[i], &Ash[wb + i * 16][k0], 40);
#pragma unroll
            for (int j = 0; j < 4; ++j)
                wmma::load_matrix_sync(bh[j], &Bs[wn + j * 16][k0], 40);
#pragma unroll
            for (int i = 0; i < 2; ++i)
#pragma unroll
                for (int j = 0; j < 4; ++j)
                    wmma::mma_sync(acc[i][j], ah[i], bh[j], acc[i][j]);
        }
    }

#pragma unroll
    for (int i = 0; i < 2; ++i)
#pragma unroll
        for (int j = 0; j < 4; ++j)
            wmma::store_matrix_sync(
                &g_P[(size_t)(b0 + wb + i * 16) * N2 + n0 + wn + j * 16],
                acc[i][j], N2, wmma::mem_row_major);
}

// ---------------------------------------------------------------------------
// joints epilogue
// ---------------------------------------------------------------------------
__global__ void k_joints(const float* __restrict__ trans,
                         float* __restrict__ out) {
    const int b = blockIdx.x;
    const int tid = threadIdx.x;
    __shared__ float sA[288];
    __shared__ float sS[456];
    for (int i = tid; i < 288; i += 64) sA[i] = g_Rg[b * 288 + i];
    for (int i = tid; i < 456; i += 64) sS[i] = g_S[i];
    __syncthreads();
    if (tid < 57) {
        int k = tid / 3, r = tid - 3 * k;
        float acc = trans[b * 3 + r];
        const float* Pb = &g_P[(size_t)b * N2];
#pragma unroll
        for (int j = 0; j < 24; ++j) {
            const float* M = &sA[j * 12];
            int m = (k * 24 + j) * 3;
            float p0 = Pb[m + 0], p1 = Pb[m + 1], p2 = Pb[m + 2];
            acc += M[r * 3 + 0] * p0 + M[r * 3 + 1] * p1 + M[r * 3 + 2] * p2 +
                   M[9 + r] * sS[k * 24 + j];
        }
        out[b * 57 + tid] = acc;
    }
}

} // namespace smpl

extern "C" void kernel_launch(void* const* d_in, const int* in_sizes, int n_in,
                              void* d_out, int out_size) {
    using namespace smpl;
    const float* beta       = (const float*)d_in[0];
    const float* theta      = (const float*)d_in[1];
    const float* trans      = (const float*)d_in[2];
    const float* v_template = (const float*)d_in[3];
    const float* shapedirs  = (const float*)d_in[4];
    const float* J_reg      = (const float*)d_in[5];
    const float* posedirs   = (const float*)d_in[6];
    const float* joint_reg  = (const float*)d_in[7];
    const float* weights    = (const float*)d_in[8];
    float* out = (float*)d_out;

    cudaFuncSetAttribute(k_gemm1_wmma,
                         cudaFuncAttributeMaxDynamicSharedMemorySize, G1_SMEM);

    // 1) build everything: Eh, Gh, JT (one launch)
    k_build<<<EB + 36 + 33, 192>>>(posedirs, shapedirs, v_template,
                                   joint_reg, weights, J_reg);

    // 2) per-body prep (depends only on JT + inputs)
    k_prep<<<B, 32>>>(beta, theta);

    // 3) GEMM1 fp16 single-term, split-K = 12
    {
        dim3 grid(N1 / 128, M1 / 256, SPLITK1);   // 6 x 2 x 12 = 144 CTAs
        k_gemm1_wmma<<<grid, 512, G1_SMEM>>>();
    }

    // 4) reduce partials -> CTt / S
    k_reduce<<<456 * 4, 128>>>();

    // 5) GEMM2 single-term fp16
    {
        dim3 grid(N2 / 128, B / 128);             // 11 x 8
        k_gemm2_wmma<<<grid, 256>>>();
    }

    // 6) joints epilogue
    k_joints<<<B, 64>>>(trans, out);
}

// round 12
// speedup vs baseline: 1.3214x; 1.3214x over previous
#include <cuda_runtime.h>
#include <cuda_fp16.h>
#include <mma.h>
#include <cstdint>

// ---------------------------------------------------------------------------
// SMPL fused pipeline, round 12: R9 skeleton + R11 wins.
//  - mega-build (E + G incl. Jreg rows), no JT tail
//  - GEMM1 fp16 single-term (256x128, 512 thr, split-K 12)
//  - high-occupancy reduce (456x4 + 24 JT blocks), zero-init pads
//  - GEMM2 single-term fp16
//  - 6 launches
// ---------------------------------------------------------------------------

namespace smpl {

constexpr int V    = 6890;
constexpr int NB   = 10;
constexpr int NJ   = 24;
constexpr int NK   = 19;
constexpr int B    = 1024;

constexpr int VP   = 6912;
constexpr int M1   = 512;
constexpr int N1   = 768;
constexpr int SPLITK1 = 12;           // KSEG = 576
constexpr int KSEG = VP / SPLITK1;
constexpr int KQ   = 256;             // 218 padded
constexpr int N2   = 1408;            // 1368 padded

// GEMM1 fp16 operands (K = v contiguous). Pads rely on zero-init.
__device__ __align__(256) __half g_Gh16[M1 * VP];
__device__ __align__(256) __half g_Eh16[N1 * VP];

// GEMM2 operands, K(=q) contiguous. Pads zero-init.
__device__ __align__(256) __half g_A2h[B * KQ];
__device__ __align__(256) __half g_CTt[N2 * KQ];

__device__ __align__(256) float g_Cp [SPLITK1 * M1 * N1];
__device__ __align__(256) float g_S  [456];
__device__ __align__(256) float g_JT [24 * 33];
__device__ __align__(256) float g_Rg [B * 288];
__device__ __align__(256) float g_P  [B * N2];

__constant__ int c_par[24] = {-1,0,0,0,1,2,3,4,5,6,7,8,9,9,9,12,13,14,16,17,18,19,20,21};

// ---------------------------------------------------------------------------
// k_build: Eh rows (241*9 blocks) + Gh rows incl. Jreg (36 blocks).
// ---------------------------------------------------------------------------
constexpr int EB = 241 * 9;           // 2169

__global__ void __launch_bounds__(192) k_build(
        const float* __restrict__ posedirs,
        const float* __restrict__ shapedirs,
        const float* __restrict__ v_template,
        const float* __restrict__ joint_reg,
        const float* __restrict__ weights,
        const float* __restrict__ J_reg) {
    const int b   = blockIdx.x;
    const int tid = threadIdx.x;

    if (b < EB) {
        const int y  = b / 9;
        const int xb = b - 9 * y;
        const int vv = (xb * 192 + tid) * 4;
        if (y < 207) {
            const int p = y;
            const float* src = posedirs + (size_t)p * (V * 3);
            float f[12];
#pragma unroll
            for (int u = 0; u < 4; ++u)
#pragma unroll
                for (int c = 0; c < 3; ++c)
                    f[3 * u + c] = (vv + u < V) ? src[3 * (vv + u) + c] : 0.f;
#pragma unroll
            for (int c = 0; c < 3; ++c) {
                __half* dst = g_Eh16 + (size_t)(3 * p + c) * VP + vv;
                *(__half2*)dst       = __floats2half2_rn(f[c], f[3 + c]);
                *(__half2*)(dst + 2) = __floats2half2_rn(f[6 + c], f[9 + c]);
            }
        } else {
            const int n = 621 + (y - 207);     // 621..654
            float f[4] = {0.f, 0.f, 0.f, 0.f};
            if (n < 651) {
                int t = n - 621, q = t / 3, c = t - 3 * q;
                const float* src = shapedirs + (size_t)q * (V * 3);
#pragma unroll
                for (int u = 0; u < 4; ++u)
                    if (vv + u < V) f[u] = src[3 * (vv + u) + c];
            } else if (n < 654) {
                int c = n - 651;
#pragma unroll
                for (int u = 0; u < 4; ++u)
                    if (vv + u < V) f[u] = v_template[3 * (vv + u) + c];
            } else {
#pragma unroll
                for (int u = 0; u < 4; ++u)
                    if (vv + u < V) f[u] = 1.f;
            }
            __half* dst = g_Eh16 + (size_t)n * VP + vv;
            *(__half2*)dst       = __floats2half2_rn(f[0], f[1]);
            *(__half2*)(dst + 2) = __floats2half2_rn(f[2], f[3]);
        }
    } else {
        const int v = (b - EB) * 192 + tid;
        const bool ok = v < V;
        float jr[NK], w[NJ];
#pragma unroll
        for (int c = 0; c < NK; ++c)
            jr[c] = ok ? joint_reg[(size_t)v * NK + c] : 0.f;
#pragma unroll
        for (int c = 0; c < NJ; ++c)
            w[c] = ok ? weights[(size_t)v * NJ + c] : 0.f;
        __half* dst = g_Gh16 + v;
        for (int k = 0; k < NK; ++k) {
            float a = jr[k];
#pragma unroll
            for (int j = 0; j < NJ; ++j)
                dst[(size_t)(k * NJ + j) * VP] = __float2half_rn(a * w[j]);
        }
        // Jreg rows 456..479 (feed JT extraction in reduce)
#pragma unroll
        for (int j = 0; j < NJ; ++j)
            dst[(size_t)(456 + j) * VP] =
                __float2half_rn(ok ? J_reg[(size_t)v * NJ + j] : 0.f);
        // rows 480..511 stay zero (zero-initialized, never written)
    }
}

// ---------------------------------------------------------------------------
// GEMM1: C[m][n] = sum_v Gh[m,v]*Eh[n,v], fp16 single term (proven R9).
// CTA 256x128, BK=32, 512 threads = 16 warps as 8m x 2n.
// ---------------------------------------------------------------------------
constexpr int G1A    = 256 * 40;
constexpr int G1B    = 128 * 40;
constexpr int G1_BUF = G1A + G1B;
constexpr int G1_SMEM = 2 * G1_BUF * 2;        // 61440 bytes

__global__ void __launch_bounds__(512, 1) k_gemm1_wmma() {
    using namespace nvcuda;
    extern __shared__ __align__(16) __half dynsmem[];

    const int n0    = blockIdx.x * 128;
    const int m0    = blockIdx.y * 256;
    const int split = blockIdx.z;
    const int tid   = threadIdx.x;
    const int wid   = tid >> 5;
    const int wm    = (wid & 7) * 32;
    const int wn    = (wid >> 3) * 64;

    wmma::fragment<wmma::accumulator, 16, 16, 16, float> acc[2][4];
#pragma unroll
    for (int i = 0; i < 2; ++i)
#pragma unroll
        for (int j = 0; j < 4; ++j)
            wmma::fill_fragment(acc[i][j], 0.f);

    const int kbase = split * KSEG;
    const int nIter = KSEG / 32;               // 18

    const int rA0 = tid >> 2;
    const int cA  = (tid & 3) * 8;

    uint4 pA[2], pB;

    auto ldg_tile = [&](int kk) {
#pragma unroll
        for (int i = 0; i < 2; ++i) {
            int row = rA0 + 128 * i;
            pA[i] = *(const uint4*)(g_Gh16 + (size_t)(m0 + row) * VP + kk + cA);
        }
        pB = *(const uint4*)(g_Eh16 + (size_t)(n0 + rA0) * VP + kk + cA);
    };
    auto sts_tile = [&](int buf) {
        __half* base = dynsmem + buf * G1_BUF;
#pragma unroll
        for (int i = 0; i < 2; ++i) {
            int row = rA0 + 128 * i;
            *(uint4*)(base + row * 40 + cA) = pA[i];
        }
        *(uint4*)(base + G1A + rA0 * 40 + cA) = pB;
    };

    ldg_tile(kbase);
    sts_tile(0);
    ldg_tile(kbase + 32);
    __syncthreads();

    for (int it = 0; it < nIter; ++it) {
        const int cur = it & 1;
        if (it + 1 < nIter) sts_tile(1 - cur);
        if (it + 2 < nIter) ldg_tile(kbase + (it + 2) * 32);

        const __half* Ah = dynsmem + cur * G1_BUF;
        const __half* Bh = Ah + G1A;
#pragma unroll
        for (int k0 = 0; k0 < 32; k0 += 16) {
            wmma::fragment<wmma::matrix_a, 16, 16, 16, __half,
                           wmma::row_major> ah[2];
            wmma::fragment<wmma::matrix_b, 16, 16, 16, __half,
                           wmma::col_major> bh[4];
#pragma unroll
            for (int i = 0; i < 2; ++i)
                wmma::load_matrix_sync(ah[i], Ah + (wm + i * 16) * 40 + k0, 40);
#pragma unroll
            for (int j = 0; j < 4; ++j)
                wmma::load_matrix_sync(bh[j], Bh + (wn + j * 16) * 40 + k0, 40);
#pragma unroll
            for (int i = 0; i < 2; ++i)
#pragma unroll
                for (int j = 0; j < 4; ++j)
                    wmma::mma_sync(acc[i][j], ah[i], bh[j], acc[i][j]);
        }
        __syncthreads();
    }

    float* Co = g_Cp + (size_t)split * (M1 * N1);
#pragma unroll
    for (int i = 0; i < 2; ++i)
#pragma unroll
        for (int j = 0; j < 4; ++j)
            wmma::store_matrix_sync(
                &Co[(size_t)(m0 + wm + i * 16) * N1 + n0 + wn + j * 16],
                acc[i][j], N1, wmma::mem_row_major);
}

// ---------------------------------------------------------------------------
// Reduce: blocks [0,1824): 456 kj-rows x 4 col-chunks -> CTt fp16 + S;
//         blocks [1824,1848): JT row j from Jreg rows of g_Cp.
// ---------------------------------------------------------------------------
__global__ void __launch_bounds__(128) k_reduce() {
    const int blk = blockIdx.x;

    if (blk < 1824) {
        const int kj    = blk >> 2;
        const int chunk = blk & 3;
        const int base  = chunk * 164;
        for (int i = threadIdx.x; i < 164; i += 128) {
            int col = base + i;
            if (col > 654) break;
            float val = 0.f;
            size_t off = (size_t)kj * N1 + col;
#pragma unroll
            for (int sp = 0; sp < SPLITK1; ++sp)
                val += g_Cp[(size_t)sp * (M1 * N1) + off];
            if (col == 654) {
                g_S[kj] = val;
            } else {
                int q, c;
                if (col < 621)      { q = 11 + col / 3; c = col - 3 * (col / 3); }
                else if (col < 651) { int t = col - 621; q = 1 + t / 3; c = t - 3 * (t / 3); }
                else                { q = 0; c = col - 651; }
                g_CTt[(size_t)(3 * kj + c) * KQ + q] = __float2half_rn(val);
            }
        }
    } else {
        const int j = blk - 1824;              // 0..23
        if (threadIdx.x < 33) {
            float val = 0.f;
            size_t off = (size_t)(456 + j) * N1 + 621 + threadIdx.x;
#pragma unroll
            for (int sp = 0; sp < SPLITK1; ++sp)
                val += g_Cp[(size_t)sp * (M1 * N1) + off];
            g_JT[j * 33 + threadIdx.x] = val;
        }
    }
}

// ---------------------------------------------------------------------------
// Per-body prep (one warp / body). Emits A2 row [b][q] as single fp16.
// ---------------------------------------------------------------------------
__global__ void k_prep(const float* __restrict__ beta,
                       const float* __restrict__ theta) {
    const int b = blockIdx.x;
    const int lane = threadIdx.x;

    __shared__ float Rsm[24][9];
    __shared__ float Jm[24][3];
    __shared__ float Ag[24][12];
    __shared__ float bet[10];

    if (lane < 10) bet[lane] = beta[b * NB + lane];
    __syncwarp();

    if (lane < 24) {
        float tx = theta[b * 72 + lane * 3 + 0];
        float ty = theta[b * 72 + lane * 3 + 1];
        float tz = theta[b * 72 + lane * 3 + 2];
        float ax = tx + 1e-8f, ay = ty + 1e-8f, az = tz + 1e-8f;
        float angle = sqrtf(ax * ax + ay * ay + az * az);
        float half = 0.5f * angle;
        float s = sinf(half), cw = cosf(half);
        float vx = tx / angle * s, vy = ty / angle * s, vz = tz / angle * s;
        float qn = sqrtf(cw * cw + vx * vx + vy * vy + vz * vz);
        float w = cw / qn, x = vx / qn, y = vy / qn, z = vz / qn;
        Rsm[lane][0] = 1.f - 2.f * (y * y + z * z);
        Rsm[lane][1] = 2.f * (x * y - w * z);
        Rsm[lane][2] = 2.f * (x * z + w * y);
        Rsm[lane][3] = 2.f * (x * y + w * z);
        Rsm[lane][4] = 1.f - 2.f * (x * x + z * z);
        Rsm[lane][5] = 2.f * (y * z - w * x);
        Rsm[lane][6] = 2.f * (x * z - w * y);
        Rsm[lane][7] = 2.f * (y * z + w * x);
        Rsm[lane][8] = 1.f - 2.f * (x * x + y * y);
#pragma unroll
        for (int c = 0; c < 3; ++c) {
            float val = g_JT[lane * 33 + 30 + c];
#pragma unroll
            for (int n = 0; n < 10; ++n)
                val += bet[n] * g_JT[lane * 33 + n * 3 + c];
            Jm[lane][c] = val;
        }
    }
    __syncwarp();

    for (int q = lane; q < 218; q += 32) {
        float val;
        if (q == 0) val = 1.f;
        else if (q <= 10) val = bet[q - 1];
        else {
            int p = q - 11;
            int i = p / 9 + 1, e = p - 9 * (p / 9);
            val = Rsm[i][e] - ((e == 0 || e == 4 || e == 8) ? 1.f : 0.f);
        }
        g_A2h[(size_t)b * KQ + q] = __float2half_rn(val);
    }

    const int r = lane >> 2, cc = lane & 3;
    for (int i = 0; i < 24; ++i) {
        if (lane < 12) {
            float val;
            if (i == 0) {
                val = (cc < 3) ? Rsm[0][r * 3 + cc] * (cc == 0 ? 1.f : -1.f)
                               : Jm[0][r];
            } else {
                int par = c_par[i];
                float l0, l1, l2;
                if (cc < 3) {
                    l0 = Rsm[i][0 * 3 + cc];
                    l1 = Rsm[i][1 * 3 + cc];
                    l2 = Rsm[i][2 * 3 + cc];
                } else {
                    l0 = Jm[i][0] - Jm[par][0];
                    l1 = Jm[i][1] - Jm[par][1];
                    l2 = Jm[i][2] - Jm[par][2];
                }
                val = Ag[par][r * 4 + 0] * l0 + Ag[par][r * 4 + 1] * l1 +
                      Ag[par][r * 4 + 2] * l2;
                if (cc == 3) val += Ag[par][r * 4 + 3];
            }
            Ag[i][r * 4 + cc] = val;
        }
        __syncwarp();
    }

    for (int idx = lane; idx < 288; idx += 32) {
        int j = idx / 12, e = idx - 12 * j;
        float out;
        if (e < 9) {
            int rr = e / 3, c = e - 3 * rr;
            out = Ag[j][rr * 4 + c];
        } else {
            int rr = e - 9;
            out = Ag[j][rr * 4 + 3] -
                  (Ag[j][rr * 4 + 0] * Jm[j][0] + Ag[j][rr * 4 + 1] * Jm[j][1] +
                   Ag[j][rr * 4 + 2] * Jm[j][2]);
        }
        g_Rg[b * 288 + idx] = out;
    }
}

// ---------------------------------------------------------------------------
// GEMM2: P[b][m] = sum_q A2h[b,q]*CTt[m,q], single-term fp16.
// CTA 128x128, BK=32, 8 warps as 4b x 2m.
// ---------------------------------------------------------------------------
__global__ void __launch_bounds__(256, 2) k_gemm2_wmma() {
    using namespace nvcuda;

    __shared__ __align__(16) __half Ash[128][40];
    __shared__ __align__(16) __half Bs [128][40];

    const int n0  = blockIdx.x * 128;
    const int b0  = blockIdx.y * 128;
    const int tid = threadIdx.x;
    const int wid = tid >> 5;
    const int wb  = (wid & 3) * 32;
    const int wn  = (wid >> 2) * 64;

    wmma::fragment<wmma::accumulator, 16, 16, 16, float> acc[2][4];
#pragma unroll
    for (int i = 0; i < 2; ++i)
#pragma unroll
        for (int j = 0; j < 4; ++j)
            wmma::fill_fragment(acc[i][j], 0.f);

    const int nIter = KQ / 32;                 // 8

    uint4 pA[2], pB[2];
    auto ldg_tile = [&](int kk) {
#pragma unroll
        for (int i = 0; i < 2; ++i) {
            int linear = tid + 256 * i;
            int row = linear >> 2, c = (linear & 3) * 8;
            pA[i] = *(const uint4*)(g_A2h + (size_t)(b0 + row) * KQ + kk + c);
            pB[i] = *(const uint4*)(g_CTt + (size_t)(n0 + row) * KQ + kk + c);
        }
    };

    ldg_tile(0);

    for (int it = 0; it < nIter; ++it) {
        __syncthreads();
#pragma unroll
        for (int i = 0; i < 2; ++i) {
            int linear = tid + 256 * i;
            int row = linear >> 2, c = (linear & 3) * 8;
            *(uint4*)&Ash[row][c] = pA[i];
            *(uint4*)&Bs[row][c]  = pB[i];
        }
        __syncthreads();
        if (it + 1 < nIter) ldg_tile((it + 1) * 32);

#pragma unroll
        for (int k0 = 0; k0 < 32; k0 += 16) {
            wmma::fragment<wmma::matrix_a, 16, 16, 16, __half,
                           wmma::row_major> ah[2];
            wmma::fragment<wmma::matrix_b, 16, 16, 16, __half,
                           wmma::col_major> bh[4];
#pragma unroll
            for (int i = 0; i < 2; ++i)
                wmma::load_matrix_sync(ah[i], &Ash[wb + i * 16][k0], 40);
#pragma unroll
            for (int j = 0; j < 4; ++j)
                wmma::load_matrix_sync(bh[j], &Bs[wn + j * 16][k0], 40);
#pragma unroll
            for (int i = 0; i < 2; ++i)
#pragma unroll
                for (int j = 0; j < 4; ++j)
                    wmma::mma_sync(acc[i][j], ah[i], bh[j], acc[i][j]);
        }
    }

#pragma unroll
    for (int i = 0; i < 2; ++i)
#pragma unroll
        for (int j = 0; j < 4; ++j)
            wmma::store_matrix_sync(
                &g_P[(size_t)(b0 + wb + i * 16) * N2 + n0 + wn + j * 16],
                acc[i][j], N2, wmma::mem_row_major);
}

// ---------------------------------------------------------------------------
// joints epilogue
// ---------------------------------------------------------------------------
__global__ void k_joints(const float* __restrict__ trans,
                         float* __restrict__ out) {
    const int b = blockIdx.x;
    const int tid = threadIdx.x;
    __shared__ float sA[288];
    __shared__ float sS[456];
    for (int i = tid; i < 288; i += 64) sA[i] = g_Rg[b * 288 + i];
    for (int i = tid; i < 456; i += 64) sS[i] = g_S[i];
    __syncthreads();
    if (tid < 57) {
        int k = tid / 3, r = tid - 3 * k;
        float acc = trans[b * 3 + r];
        const float* Pb = &g_P[(size_t)b * N2];
#pragma unroll
        for (int j = 0; j < 24; ++j) {
            const float* M = &sA[j * 12];
            int m = (k * 24 + j) * 3;
            float p0 = Pb[m + 0], p1 = Pb[m + 1], p2 = Pb[m + 2];
            acc += M[r * 3 + 0] * p0 + M[r * 3 + 1] * p1 + M[r * 3 + 2] * p2 +
                   M[9 + r] * sS[k * 24 + j];
        }
        out[b * 57 + tid] = acc;
    }
}

} // namespace smpl

extern "C" void kernel_launch(void* const* d_in, const int* in_sizes, int n_in,
                              void* d_out, int out_size) {
    using namespace smpl;
    const float* beta       = (const float*)d_in[0];
    const float* theta      = (const float*)d_in[1];
    const float* trans      = (const float*)d_in[2];
    const float* v_template = (const float*)d_in[3];
    const float* shapedirs  = (const float*)d_in[4];
    const float* J_reg      = (const float*)d_in[5];
    const float* posedirs   = (const float*)d_in[6];
    const float* joint_reg  = (const float*)d_in[7];
    const float* weights    = (const float*)d_in[8];
    float* out = (float*)d_out;

    cudaFuncSetAttribute(k_gemm1_wmma,
                         cudaFuncAttributeMaxDynamicSharedMemorySize, G1_SMEM);

    // 1) build Eh + Gh (incl. Jreg rows), one launch
    k_build<<<EB + 36, 192>>>(posedirs, shapedirs, v_template,
                              joint_reg, weights, J_reg);

    // 2) GEMM1 fp16 single-term, split-K = 12
    {
        dim3 grid(N1 / 128, M1 / 256, SPLITK1);   // 6 x 2 x 12 = 144 CTAs
        k_gemm1_wmma<<<grid, 512, G1_SMEM>>>();
    }

    // 3) reduce partials -> CTt / S / JT
    k_reduce<<<456 * 4 + 24, 128>>>();

    // 4) per-body prep (needs JT)
    k_prep<<<B, 32>>>(beta, theta);

    // 5) GEMM2 single-term fp16
    {
        dim3 grid(N2 / 128, B / 128);             // 11 x 8
        k_gemm2_wmma<<<grid, 256>>>();
    }

    // 6) joints epilogue
    k_joints<<<B, 64>>>(trans, out);
}

// round 13
// speedup vs baseline: 1.3399x; 1.0140x over previous
#include <cuda_runtime.h>
#include <cuda_fp16.h>
#include <mma.h>
#include <cstdint>

// ---------------------------------------------------------------------------
// SMPL fused pipeline, round 13: R12 + occupancy-packed prep (8 bodies/CTA)
// and joints (4 bodies/CTA).
// ---------------------------------------------------------------------------

namespace smpl {

constexpr int V    = 6890;
constexpr int NB   = 10;
constexpr int NJ   = 24;
constexpr int NK   = 19;
constexpr int B    = 1024;

constexpr int VP   = 6912;
constexpr int M1   = 512;
constexpr int N1   = 768;
constexpr int SPLITK1 = 12;           // KSEG = 576
constexpr int KSEG = VP / SPLITK1;
constexpr int KQ   = 256;             // 218 padded
constexpr int N2   = 1408;            // 1368 padded

// GEMM1 fp16 operands (K = v contiguous). Pads rely on zero-init.
__device__ __align__(256) __half g_Gh16[M1 * VP];
__device__ __align__(256) __half g_Eh16[N1 * VP];

// GEMM2 operands, K(=q) contiguous. Pads zero-init.
__device__ __align__(256) __half g_A2h[B * KQ];
__device__ __align__(256) __half g_CTt[N2 * KQ];

__device__ __align__(256) float g_Cp [SPLITK1 * M1 * N1];
__device__ __align__(256) float g_S  [456];
__device__ __align__(256) float g_JT [24 * 33];
__device__ __align__(256) float g_Rg [B * 288];
__device__ __align__(256) float g_P  [B * N2];

__constant__ int c_par[24] = {-1,0,0,0,1,2,3,4,5,6,7,8,9,9,9,12,13,14,16,17,18,19,20,21};

// ---------------------------------------------------------------------------
// k_build: Eh rows (241*9 blocks) + Gh rows incl. Jreg (36 blocks).
// ---------------------------------------------------------------------------
constexpr int EB = 241 * 9;           // 2169

__global__ void __launch_bounds__(192) k_build(
        const float* __restrict__ posedirs,
        const float* __restrict__ shapedirs,
        const float* __restrict__ v_template,
        const float* __restrict__ joint_reg,
        const float* __restrict__ weights,
        const float* __restrict__ J_reg) {
    const int b   = blockIdx.x;
    const int tid = threadIdx.x;

    if (b < EB) {
        const int y  = b / 9;
        const int xb = b - 9 * y;
        const int vv = (xb * 192 + tid) * 4;
        if (y < 207) {
            const int p = y;
            const float* src = posedirs + (size_t)p * (V * 3);
            float f[12];
#pragma unroll
            for (int u = 0; u < 4; ++u)
#pragma unroll
                for (int c = 0; c < 3; ++c)
                    f[3 * u + c] = (vv + u < V) ? src[3 * (vv + u) + c] : 0.f;
#pragma unroll
            for (int c = 0; c < 3; ++c) {
                __half* dst = g_Eh16 + (size_t)(3 * p + c) * VP + vv;
                *(__half2*)dst       = __floats2half2_rn(f[c], f[3 + c]);
                *(__half2*)(dst + 2) = __floats2half2_rn(f[6 + c], f[9 + c]);
            }
        } else {
            const int n = 621 + (y - 207);     // 621..654
            float f[4] = {0.f, 0.f, 0.f, 0.f};
            if (n < 651) {
                int t = n - 621, q = t / 3, c = t - 3 * q;
                const float* src = shapedirs + (size_t)q * (V * 3);
#pragma unroll
                for (int u = 0; u < 4; ++u)
                    if (vv + u < V) f[u] = src[3 * (vv + u) + c];
            } else if (n < 654) {
                int c = n - 651;
#pragma unroll
                for (int u = 0; u < 4; ++u)
                    if (vv + u < V) f[u] = v_template[3 * (vv + u) + c];
            } else {
#pragma unroll
                for (int u = 0; u < 4; ++u)
                    if (vv + u < V) f[u] = 1.f;
            }
            __half* dst = g_Eh16 + (size_t)n * VP + vv;
            *(__half2*)dst       = __floats2half2_rn(f[0], f[1]);
            *(__half2*)(dst + 2) = __floats2half2_rn(f[2], f[3]);
        }
    } else {
        const int v = (b - EB) * 192 + tid;
        const bool ok = v < V;
        float jr[NK], w[NJ];
#pragma unroll
        for (int c = 0; c < NK; ++c)
            jr[c] = ok ? joint_reg[(size_t)v * NK + c] : 0.f;
#pragma unroll
        for (int c = 0; c < NJ; ++c)
            w[c] = ok ? weights[(size_t)v * NJ + c] : 0.f;
        __half* dst = g_Gh16 + v;
        for (int k = 0; k < NK; ++k) {
            float a = jr[k];
#pragma unroll
            for (int j = 0; j < NJ; ++j)
                dst[(size_t)(k * NJ + j) * VP] = __float2half_rn(a * w[j]);
        }
#pragma unroll
        for (int j = 0; j < NJ; ++j)
            dst[(size_t)(456 + j) * VP] =
                __float2half_rn(ok ? J_reg[(size_t)v * NJ + j] : 0.f);
        // rows 480..511 stay zero (zero-initialized, never written)
    }
}

// ---------------------------------------------------------------------------
// GEMM1: C[m][n] = sum_v Gh[m,v]*Eh[n,v], fp16 single term.
// CTA 256x128, BK=32, 512 threads = 16 warps as 8m x 2n.
// ---------------------------------------------------------------------------
constexpr int G1A    = 256 * 40;
constexpr int G1B    = 128 * 40;
constexpr int G1_BUF = G1A + G1B;
constexpr int G1_SMEM = 2 * G1_BUF * 2;        // 61440 bytes

__global__ void __launch_bounds__(512, 1) k_gemm1_wmma() {
    using namespace nvcuda;
    extern __shared__ __align__(16) __half dynsmem[];

    const int n0    = blockIdx.x * 128;
    const int m0    = blockIdx.y * 256;
    const int split = blockIdx.z;
    const int tid   = threadIdx.x;
    const int wid   = tid >> 5;
    const int wm    = (wid & 7) * 32;
    const int wn    = (wid >> 3) * 64;

    wmma::fragment<wmma::accumulator, 16, 16, 16, float> acc[2][4];
#pragma unroll
    for (int i = 0; i < 2; ++i)
#pragma unroll
        for (int j = 0; j < 4; ++j)
            wmma::fill_fragment(acc[i][j], 0.f);

    const int kbase = split * KSEG;
    const int nIter = KSEG / 32;               // 18

    const int rA0 = tid >> 2;
    const int cA  = (tid & 3) * 8;

    uint4 pA[2], pB;

    auto ldg_tile = [&](int kk) {
#pragma unroll
        for (int i = 0; i < 2; ++i) {
            int row = rA0 + 128 * i;
            pA[i] = *(const uint4*)(g_Gh16 + (size_t)(m0 + row) * VP + kk + cA);
        }
        pB = *(const uint4*)(g_Eh16 + (size_t)(n0 + rA0) * VP + kk + cA);
    };
    auto sts_tile = [&](int buf) {
        __half* base = dynsmem + buf * G1_BUF;
#pragma unroll
        for (int i = 0; i < 2; ++i) {
            int row = rA0 + 128 * i;
            *(uint4*)(base + row * 40 + cA) = pA[i];
        }
        *(uint4*)(base + G1A + rA0 * 40 + cA) = pB;
    };

    ldg_tile(kbase);
    sts_tile(0);
    ldg_tile(kbase + 32);
    __syncthreads();

    for (int it = 0; it < nIter; ++it) {
        const int cur = it & 1;
        if (it + 1 < nIter) sts_tile(1 - cur);
        if (it + 2 < nIter) ldg_tile(kbase + (it + 2) * 32);

        const __half* Ah = dynsmem + cur * G1_BUF;
        const __half* Bh = Ah + G1A;
#pragma unroll
        for (int k0 = 0; k0 < 32; k0 += 16) {
            wmma::fragment<wmma::matrix_a, 16, 16, 16, __half,
                           wmma::row_major> ah[2];
            wmma::fragment<wmma::matrix_b, 16, 16, 16, __half,
                           wmma::col_major> bh[4];
#pragma unroll
            for (int i = 0; i < 2; ++i)
                wmma::load_matrix_sync(ah[i], Ah + (wm + i * 16) * 40 + k0, 40);
#pragma unroll
            for (int j = 0; j < 4; ++j)
                wmma::load_matrix_sync(bh[j], Bh + (wn + j * 16) * 40 + k0, 40);
#pragma unroll
            for (int i = 0; i < 2; ++i)
#pragma unroll
                for (int j = 0; j < 4; ++j)
                    wmma::mma_sync(acc[i][j], ah[i], bh[j], acc[i][j]);
        }
        __syncthreads();
    }

    float* Co = g_Cp + (size_t)split * (M1 * N1);
#pragma unroll
    for (int i = 0; i < 2; ++i)
#pragma unroll
        for (int j = 0; j < 4; ++j)
            wmma::store_matrix_sync(
                &Co[(size_t)(m0 + wm + i * 16) * N1 + n0 + wn + j * 16],
                acc[i][j], N1, wmma::mem_row_major);
}

// ---------------------------------------------------------------------------
// Reduce: blocks [0,1824): CTt fp16 + S; blocks [1824,1848): JT.
// ---------------------------------------------------------------------------
__global__ void __launch_bounds__(128) k_reduce() {
    const int blk = blockIdx.x;

    if (blk < 1824) {
        const int kj    = blk >> 2;
        const int chunk = blk & 3;
        const int base  = chunk * 164;
        for (int i = threadIdx.x; i < 164; i += 128) {
            int col = base + i;
            if (col > 654) break;
            float val = 0.f;
            size_t off = (size_t)kj * N1 + col;
#pragma unroll
            for (int sp = 0; sp < SPLITK1; ++sp)
                val += g_Cp[(size_t)sp * (M1 * N1) + off];
            if (col == 654) {
                g_S[kj] = val;
            } else {
                int q, c;
                if (col < 621)      { q = 11 + col / 3; c = col - 3 * (col / 3); }
                else if (col < 651) { int t = col - 621; q = 1 + t / 3; c = t - 3 * (t / 3); }
                else                { q = 0; c = col - 651; }
                g_CTt[(size_t)(3 * kj + c) * KQ + q] = __float2half_rn(val);
            }
        }
    } else {
        const int j = blk - 1824;              // 0..23
        if (threadIdx.x < 33) {
            float val = 0.f;
            size_t off = (size_t)(456 + j) * N1 + 621 + threadIdx.x;
#pragma unroll
            for (int sp = 0; sp < SPLITK1; ++sp)
                val += g_Cp[(size_t)sp * (M1 * N1) + off];
            g_JT[j * 33 + threadIdx.x] = val;
        }
    }
}

// ---------------------------------------------------------------------------
// Per-body prep: 8 bodies per CTA (256 threads, one warp per body).
// ---------------------------------------------------------------------------
__global__ void __launch_bounds__(256) k_prep(const float* __restrict__ beta,
                                              const float* __restrict__ theta) {
    const int wrp  = threadIdx.x >> 5;       // 0..7 body slot
    const int lane = threadIdx.x & 31;
    const int b    = blockIdx.x * 8 + wrp;

    __shared__ float Rsm[8][24][9];
    __shared__ float Jm [8][24][3];
    __shared__ float Ag [8][24][12];
    __shared__ float bet[8][10];

    if (lane < 10) bet[wrp][lane] = beta[b * NB + lane];
    __syncwarp();

    if (lane < 24) {
        float tx = theta[b * 72 + lane * 3 + 0];
        float ty = theta[b * 72 + lane * 3 + 1];
        float tz = theta[b * 72 + lane * 3 + 2];
        float ax = tx + 1e-8f, ay = ty + 1e-8f, az = tz + 1e-8f;
        float angle = sqrtf(ax * ax + ay * ay + az * az);
        float half = 0.5f * angle;
        float s = sinf(half), cw = cosf(half);
        float vx = tx / angle * s, vy = ty / angle * s, vz = tz / angle * s;
        float qn = sqrtf(cw * cw + vx * vx + vy * vy + vz * vz);
        float w = cw / qn, x = vx / qn, y = vy / qn, z = vz / qn;
        Rsm[wrp][lane][0] = 1.f - 2.f * (y * y + z * z);
        Rsm[wrp][lane][1] = 2.f * (x * y - w * z);
        Rsm[wrp][lane][2] = 2.f * (x * z + w * y);
        Rsm[wrp][lane][3] = 2.f * (x * y + w * z);
        Rsm[wrp][lane][4] = 1.f - 2.f * (x * x + z * z);
        Rsm[wrp][lane][5] = 2.f * (y * z - w * x);
        Rsm[wrp][lane][6] = 2.f * (x * z - w * y);
        Rsm[wrp][lane][7] = 2.f * (y * z + w * x);
        Rsm[wrp][lane][8] = 1.f - 2.f * (x * x + y * y);
#pragma unroll
        for (int c = 0; c < 3; ++c) {
            float val = g_JT[lane * 33 + 30 + c];
#pragma unroll
            for (int n = 0; n < 10; ++n)
                val += bet[wrp][n] * g_JT[lane * 33 + n * 3 + c];
            Jm[wrp][lane][c] = val;
        }
    }
    __syncwarp();

    for (int q = lane; q < 218; q += 32) {
        float val;
        if (q == 0) val = 1.f;
        else if (q <= 10) val = bet[wrp][q - 1];
        else {
            int p = q - 11;
            int i = p / 9 + 1, e = p - 9 * (p / 9);
            val = Rsm[wrp][i][e] - ((e == 0 || e == 4 || e == 8) ? 1.f : 0.f);
        }
        g_A2h[(size_t)b * KQ + q] = __float2half_rn(val);
    }

    const int r = lane >> 2, cc = lane & 3;
    for (int i = 0; i < 24; ++i) {
        if (lane < 12) {
            float val;
            if (i == 0) {
                val = (cc < 3) ? Rsm[wrp][0][r * 3 + cc] * (cc == 0 ? 1.f : -1.f)
                               : Jm[wrp][0][r];
            } else {
                int par = c_par[i];
                float l0, l1, l2;
                if (cc < 3) {
                    l0 = Rsm[wrp][i][0 * 3 + cc];
                    l1 = Rsm[wrp][i][1 * 3 + cc];
                    l2 = Rsm[wrp][i][2 * 3 + cc];
                } else {
                    l0 = Jm[wrp][i][0] - Jm[wrp][par][0];
                    l1 = Jm[wrp][i][1] - Jm[wrp][par][1];
                    l2 = Jm[wrp][i][2] - Jm[wrp][par][2];
                }
                val = Ag[wrp][par][r * 4 + 0] * l0 + Ag[wrp][par][r * 4 + 1] * l1 +
                      Ag[wrp][par][r * 4 + 2] * l2;
                if (cc == 3) val += Ag[wrp][par][r * 4 + 3];
            }
            Ag[wrp][i][r * 4 + cc] = val;
        }
        __syncwarp();
    }

    for (int idx = lane; idx < 288; idx += 32) {
        int j = idx / 12, e = idx - 12 * j;
        float out;
        if (e < 9) {
            int rr = e / 3, c = e - 3 * rr;
            out = Ag[wrp][j][rr * 4 + c];
        } else {
            int rr = e - 9;
            out = Ag[wrp][j][rr * 4 + 3] -
                  (Ag[wrp][j][rr * 4 + 0] * Jm[wrp][j][0] +
                   Ag[wrp][j][rr * 4 + 1] * Jm[wrp][j][1] +
                   Ag[wrp][j][rr * 4 + 2] * Jm[wrp][j][2]);
        }
        g_Rg[b * 288 + idx] = out;
    }
}

// ---------------------------------------------------------------------------
// GEMM2: P[b][m] = sum_q A2h[b,q]*CTt[m,q], single-term fp16.
// ---------------------------------------------------------------------------
__global__ void __launch_bounds__(256, 2) k_gemm2_wmma() {
    using namespace nvcuda;

    __shared__ __align__(16) __half Ash[128][40];
    __shared__ __align__(16) __half Bs [128][40];

    const int n0  = blockIdx.x * 128;
    const int b0  = blockIdx.y * 128;
    const int tid = threadIdx.x;
    const int wid = tid >> 5;
    const int wb  = (wid & 3) * 32;
    const int wn  = (wid >> 2) * 64;

    wmma::fragment<wmma::accumulator, 16, 16, 16, float> acc[2][4];
#pragma unroll
    for (int i = 0; i < 2; ++i)
#pragma unroll
        for (int j = 0; j < 4; ++j)
            wmma::fill_fragment(acc[i][j], 0.f);

    const int nIter = KQ / 32;                 // 8

    uint4 pA[2], pB[2];
    auto ldg_tile = [&](int kk) {
#pragma unroll
        for (int i = 0; i < 2; ++i) {
            int linear = tid + 256 * i;
            int row = linear >> 2, c = (linear & 3) * 8;
            pA[i] = *(const uint4*)(g_A2h + (size_t)(b0 + row) * KQ + kk + c);
            pB[i] = *(const uint4*)(g_CTt + (size_t)(n0 + row) * KQ + kk + c);
        }
    };

    ldg_tile(0);

    for (int it = 0; it < nIter; ++it) {
        __syncthreads();
#pragma unroll
        for (int i = 0; i < 2; ++i) {
            int linear = tid + 256 * i;
            int row = linear >> 2, c = (linear & 3) * 8;
            *(uint4*)&Ash[row][c] = pA[i];
            *(uint4*)&Bs[row][c]  = pB[i];
        }
        __syncthreads();
        if (it + 1 < nIter) ldg_tile((it + 1) * 32);

#pragma unroll
        for (int k0 = 0; k0 < 32; k0 += 16) {
            wmma::fragment<wmma::matrix_a, 16, 16, 16, __half,
                           wmma::row_major> ah[2];
            wmma::fragment<wmma::matrix_b, 16, 16, 16, __half,
                           wmma::col_major> bh[4];
#pragma unroll
            for (int i = 0; i < 2; ++i)
                wmma::load_matrix_sync(ah[i], &Ash[wb + i * 16][k0], 40);
#pragma unroll
            for (int j = 0; j < 4; ++j)
                wmma::load_matrix_sync(bh[j], &Bs[wn + j * 16][k0], 40);
#pragma unroll
            for (int i = 0; i < 2; ++i)
#pragma unroll
                for (int j = 0; j < 4; ++j)
                    wmma::mma_sync(acc[i][j], ah[i], bh[j], acc[i][j]);
        }
    }

#pragma unroll
    for (int i = 0; i < 2; ++i)
#pragma unroll
        for (int j = 0; j < 4; ++j)
            wmma::store_matrix_sync(
                &g_P[(size_t)(b0 + wb + i * 16) * N2 + n0 + wn + j * 16],
                acc[i][j], N2, wmma::mem_row_major);
}

// ---------------------------------------------------------------------------
// joints epilogue: 4 bodies per CTA (256 threads), sS loaded once per CTA.
// ---------------------------------------------------------------------------
__global__ void __launch_bounds__(256) k_joints(const float* __restrict__ trans,
                                                float* __restrict__ out) {
    const int grp = threadIdx.x >> 6;          // 0..3 body slot
    const int t   = threadIdx.x & 63;
    const int b   = blockIdx.x * 4 + grp;

    __shared__ float sA[4][288];
    __shared__ float sS[456];

    for (int i = threadIdx.x; i < 456; i += 256) sS[i] = g_S[i];
    for (int i = t; i < 288; i += 64) sA[grp][i] = g_Rg[b * 288 + i];
    __syncthreads();

    if (t < 57) {
        int k = t / 3, r = t - 3 * k;
        float acc = trans[b * 3 + r];
        const float* Pb = &g_P[(size_t)b * N2];
#pragma unroll
        for (int j = 0; j < 24; ++j) {
            const float* M = &sA[grp][j * 12];
            int m = (k * 24 + j) * 3;
            float p0 = Pb[m + 0], p1 = Pb[m + 1], p2 = Pb[m + 2];
            acc += M[r * 3 + 0] * p0 + M[r * 3 + 1] * p1 + M[r * 3 + 2] * p2 +
                   M[9 + r] * sS[k * 24 + j];
        }
        out[b * 57 + t] = acc;
    }
}

} // namespace smpl

extern "C" void kernel_launch(void* const* d_in, const int* in_sizes, int n_in,
                              void* d_out, int out_size) {
    using namespace smpl;
    const float* beta       = (const float*)d_in[0];
    const float* theta      = (const float*)d_in[1];
    const float* trans      = (const float*)d_in[2];
    const float* v_template = (const float*)d_in[3];
    const float* shapedirs  = (const float*)d_in[4];
    const float* J_reg      = (const float*)d_in[5];
    const float* posedirs   = (const float*)d_in[6];
    const float* joint_reg  = (const float*)d_in[7];
    const float* weights    = (const float*)d_in[8];
    float* out = (float*)d_out;

    cudaFuncSetAttribute(k_gemm1_wmma,
                         cudaFuncAttributeMaxDynamicSharedMemorySize, G1_SMEM);

    // 1) build Eh + Gh (incl. Jreg rows)
    k_build<<<EB + 36, 192>>>(posedirs, shapedirs, v_template,
                              joint_reg, weights, J_reg);

    // 2) GEMM1 fp16 single-term, split-K = 12
    {
        dim3 grid(N1 / 128, M1 / 256, SPLITK1);   // 6 x 2 x 12 = 144 CTAs
        k_gemm1_wmma<<<grid, 512, G1_SMEM>>>();
    }

    // 3) reduce partials -> CTt / S / JT
    k_reduce<<<456 * 4 + 24, 128>>>();

    // 4) per-body prep, 8 bodies per CTA
    k_prep<<<B / 8, 256>>>(beta, theta);

    // 5) GEMM2 single-term fp16
    {
        dim3 grid(N2 / 128, B / 128);             // 11 x 8
        k_gemm2_wmma<<<grid, 256>>>();
    }

    // 6) joints epilogue, 4 bodies per CTA
    k_joints<<<B / 4, 256>>>(trans, out);
}

// round 14
// speedup vs baseline: 1.3896x; 1.0371x over previous
#include <cuda_runtime.h>
#include <cuda_fp16.h>
#include <mma.h>
#include <cstdint>

// ---------------------------------------------------------------------------
// SMPL fused pipeline, round 14:
//  - k_prep: 1 body / 288-thread CTA, level-parallel kinematic chain
//  - GEMM1: 128x128 tiles, split-K 6, 2 CTAs/SM  (Cp halved)
//  - reduce: 6 planes
// ---------------------------------------------------------------------------

namespace smpl {

constexpr int V    = 6890;
constexpr int NB   = 10;
constexpr int NJ   = 24;
constexpr int NK   = 19;
constexpr int B    = 1024;

constexpr int VP   = 6912;
constexpr int M1   = 512;
constexpr int N1   = 768;
constexpr int SPLITK1 = 6;            // KSEG = 1152 = 36*32
constexpr int KSEG = VP / SPLITK1;
constexpr int KQ   = 256;             // 218 padded
constexpr int N2   = 1408;            // 1368 padded

__device__ __align__(256) __half g_Gh16[M1 * VP];
__device__ __align__(256) __half g_Eh16[N1 * VP];
__device__ __align__(256) __half g_A2h[B * KQ];
__device__ __align__(256) __half g_CTt[N2 * KQ];

__device__ __align__(256) float g_Cp [SPLITK1 * M1 * N1];
__device__ __align__(256) float g_S  [456];
__device__ __align__(256) float g_JT [24 * 33];
__device__ __align__(256) float g_Rg [B * 288];
__device__ __align__(256) float g_P  [B * N2];

__constant__ int c_par[24] = {-1,0,0,0,1,2,3,4,5,6,7,8,9,9,9,12,13,14,16,17,18,19,20,21};
// kinematic tree levels: joints 0..23 are already level-ordered
__constant__ int c_lvl[10] = {0, 1, 4, 7, 10, 15, 18, 20, 22, 24};

// ---------------------------------------------------------------------------
// k_build: Eh rows (241*9 blocks) + Gh rows incl. Jreg (36 blocks).
// ---------------------------------------------------------------------------
constexpr int EB = 241 * 9;           // 2169

__global__ void __launch_bounds__(192) k_build(
        const float* __restrict__ posedirs,
        const float* __restrict__ shapedirs,
        const float* __restrict__ v_template,
        const float* __restrict__ joint_reg,
        const float* __restrict__ weights,
        const float* __restrict__ J_reg) {
    const int b   = blockIdx.x;
    const int tid = threadIdx.x;

    if (b < EB) {
        const int y  = b / 9;
        const int xb = b - 9 * y;
        const int vv = (xb * 192 + tid) * 4;
        if (y < 207) {
            const int p = y;
            const float* src = posedirs + (size_t)p * (V * 3);
            float f[12];
#pragma unroll
            for (int u = 0; u < 4; ++u)
#pragma unroll
                for (int c = 0; c < 3; ++c)
                    f[3 * u + c] = (vv + u < V) ? src[3 * (vv + u) + c] : 0.f;
#pragma unroll
            for (int c = 0; c < 3; ++c) {
                __half* dst = g_Eh16 + (size_t)(3 * p + c) * VP + vv;
                *(__half2*)dst       = __floats2half2_rn(f[c], f[3 + c]);
                *(__half2*)(dst + 2) = __floats2half2_rn(f[6 + c], f[9 + c]);
            }
        } else {
            const int n = 621 + (y - 207);     // 621..654
            float f[4] = {0.f, 0.f, 0.f, 0.f};
            if (n < 651) {
                int t = n - 621, q = t / 3, c = t - 3 * q;
                const float* src = shapedirs + (size_t)q * (V * 3);
#pragma unroll
                for (int u = 0; u < 4; ++u)
                    if (vv + u < V) f[u] = src[3 * (vv + u) + c];
            } else if (n < 654) {
                int c = n - 651;
#pragma unroll
                for (int u = 0; u < 4; ++u)
                    if (vv + u < V) f[u] = v_template[3 * (vv + u) + c];
            } else {
#pragma unroll
                for (int u = 0; u < 4; ++u)
                    if (vv + u < V) f[u] = 1.f;
            }
            __half* dst = g_Eh16 + (size_t)n * VP + vv;
            *(__half2*)dst       = __floats2half2_rn(f[0], f[1]);
            *(__half2*)(dst + 2) = __floats2half2_rn(f[2], f[3]);
        }
    } else {
        const int v = (b - EB) * 192 + tid;
        const bool ok = v < V;
        float jr[NK], w[NJ];
#pragma unroll
        for (int c = 0; c < NK; ++c)
            jr[c] = ok ? joint_reg[(size_t)v * NK + c] : 0.f;
#pragma unroll
        for (int c = 0; c < NJ; ++c)
            w[c] = ok ? weights[(size_t)v * NJ + c] : 0.f;
        __half* dst = g_Gh16 + v;
        for (int k = 0; k < NK; ++k) {
            float a = jr[k];
#pragma unroll
            for (int j = 0; j < NJ; ++j)
                dst[(size_t)(k * NJ + j) * VP] = __float2half_rn(a * w[j]);
        }
#pragma unroll
        for (int j = 0; j < NJ; ++j)
            dst[(size_t)(456 + j) * VP] =
                __float2half_rn(ok ? J_reg[(size_t)v * NJ + j] : 0.f);
        // rows 480..511 stay zero (zero-initialized, never written)
    }
}

// ---------------------------------------------------------------------------
// GEMM1: C[m][n] = sum_v Gh[m,v]*Eh[n,v], fp16 single term.
// CTA 128x128, BK=32, 256 threads = 8 warps (4m x 2n, 32x64/warp), 2 CTA/SM,
// double-buffered dynamic smem (40KB).
// ---------------------------------------------------------------------------
constexpr int G1A    = 128 * 40;               // A plane (halves)
constexpr int G1B    = 128 * 40;               // B plane
constexpr int G1_BUF = G1A + G1B;
constexpr int G1_SMEM = 2 * G1_BUF * 2;        // 40960 bytes

__global__ void __launch_bounds__(256, 2) k_gemm1_wmma() {
    using namespace nvcuda;
    extern __shared__ __align__(16) __half dynsmem[];

    const int n0    = blockIdx.x * 128;
    const int m0    = blockIdx.y * 128;
    const int split = blockIdx.z;
    const int tid   = threadIdx.x;
    const int wid   = tid >> 5;
    const int wm    = (wid & 3) * 32;
    const int wn    = (wid >> 2) * 64;

    wmma::fragment<wmma::accumulator, 16, 16, 16, float> acc[2][4];
#pragma unroll
    for (int i = 0; i < 2; ++i)
#pragma unroll
        for (int j = 0; j < 4; ++j)
            wmma::fill_fragment(acc[i][j], 0.f);

    const int kbase = split * KSEG;
    const int nIter = KSEG / 32;               // 36

    const int r = tid >> 2;                    // 0..63
    const int c = (tid & 3) * 8;

    uint4 pA[2], pB[2];

    auto ldg_tile = [&](int kk) {
#pragma unroll
        for (int i = 0; i < 2; ++i) {
            int row = r + 64 * i;
            pA[i] = *(const uint4*)(g_Gh16 + (size_t)(m0 + row) * VP + kk + c);
            pB[i] = *(const uint4*)(g_Eh16 + (size_t)(n0 + row) * VP + kk + c);
        }
    };
    auto sts_tile = [&](int buf) {
        __half* base = dynsmem + buf * G1_BUF;
#pragma unroll
        for (int i = 0; i < 2; ++i) {
            int row = r + 64 * i;
            *(uint4*)(base + row * 40 + c)       = pA[i];
            *(uint4*)(base + G1A + row * 40 + c) = pB[i];
        }
    };

    ldg_tile(kbase);
    sts_tile(0);
    ldg_tile(kbase + 32);
    __syncthreads();

    for (int it = 0; it < nIter; ++it) {
        const int cur = it & 1;
        if (it + 1 < nIter) sts_tile(1 - cur);
        if (it + 2 < nIter) ldg_tile(kbase + (it + 2) * 32);

        const __half* Ah = dynsmem + cur * G1_BUF;
        const __half* Bh = Ah + G1A;
#pragma unroll
        for (int k0 = 0; k0 < 32; k0 += 16) {
            wmma::fragment<wmma::matrix_a, 16, 16, 16, __half,
                           wmma::row_major> ah[2];
            wmma::fragment<wmma::matrix_b, 16, 16, 16, __half,
                           wmma::col_major> bh[4];
#pragma unroll
            for (int i = 0; i < 2; ++i)
                wmma::load_matrix_sync(ah[i], Ah + (wm + i * 16) * 40 + k0, 40);
#pragma unroll
            for (int j = 0; j < 4; ++j)
                wmma::load_matrix_sync(bh[j], Bh + (wn + j * 16) * 40 + k0, 40);
#pragma unroll
            for (int i = 0; i < 2; ++i)
#pragma unroll
                for (int j = 0; j < 4; ++j)
                    wmma::mma_sync(acc[i][j], ah[i], bh[j], acc[i][j]);
        }
        __syncthreads();
    }

    float* Co = g_Cp + (size_t)split * (M1 * N1);
#pragma unroll
    for (int i = 0; i < 2; ++i)
#pragma unroll
        for (int j = 0; j < 4; ++j)
            wmma::store_matrix_sync(
                &Co[(size_t)(m0 + wm + i * 16) * N1 + n0 + wn + j * 16],
                acc[i][j], N1, wmma::mem_row_major);
}

// ---------------------------------------------------------------------------
// Reduce: blocks [0,1824): CTt fp16 + S; blocks [1824,1848): JT.
// ---------------------------------------------------------------------------
__global__ void __launch_bounds__(128) k_reduce() {
    const int blk = blockIdx.x;

    if (blk < 1824) {
        const int kj    = blk >> 2;
        const int chunk = blk & 3;
        const int base  = chunk * 164;
        for (int i = threadIdx.x; i < 164; i += 128) {
            int col = base + i;
            if (col > 654) break;
            float val = 0.f;
            size_t off = (size_t)kj * N1 + col;
#pragma unroll
            for (int sp = 0; sp < SPLITK1; ++sp)
                val += g_Cp[(size_t)sp * (M1 * N1) + off];
            if (col == 654) {
                g_S[kj] = val;
            } else {
                int q, c;
                if (col < 621)      { q = 11 + col / 3; c = col - 3 * (col / 3); }
                else if (col < 651) { int t = col - 621; q = 1 + t / 3; c = t - 3 * (t / 3); }
                else                { q = 0; c = col - 651; }
                g_CTt[(size_t)(3 * kj + c) * KQ + q] = __float2half_rn(val);
            }
        }
    } else {
        const int j = blk - 1824;              // 0..23
        if (threadIdx.x < 33) {
            float val = 0.f;
            size_t off = (size_t)(456 + j) * N1 + 621 + threadIdx.x;
#pragma unroll
            for (int sp = 0; sp < SPLITK1; ++sp)
                val += g_Cp[(size_t)sp * (M1 * N1) + off];
            g_JT[j * 33 + threadIdx.x] = val;
        }
    }
}

// ---------------------------------------------------------------------------
// k_prep: ONE body per CTA of 288 threads. Level-parallel kinematic chain.
// ---------------------------------------------------------------------------
__global__ void __launch_bounds__(288) k_prep(const float* __restrict__ beta,
                                              const float* __restrict__ theta) {
    const int b = blockIdx.x;
    const int t = threadIdx.x;

    __shared__ float Rsm[24][9];
    __shared__ float Jm[24][3];
    __shared__ float Ag[24][12];
    __shared__ float bet[10];

    if (t < 10) bet[t] = beta[b * NB + t];
    __syncthreads();

    // Rodrigues on threads 0..23; J regression on threads 96..167 (parallel)
    if (t < 24) {
        float tx = theta[b * 72 + t * 3 + 0];
        float ty = theta[b * 72 + t * 3 + 1];
        float tz = theta[b * 72 + t * 3 + 2];
        float ax = tx + 1e-8f, ay = ty + 1e-8f, az = tz + 1e-8f;
        float angle = sqrtf(ax * ax + ay * ay + az * az);
        float half = 0.5f * angle;
        float s = sinf(half), cw = cosf(half);
        float vx = tx / angle * s, vy = ty / angle * s, vz = tz / angle * s;
        float qn = sqrtf(cw * cw + vx * vx + vy * vy + vz * vz);
        float w = cw / qn, x = vx / qn, y = vy / qn, z = vz / qn;
        Rsm[t][0] = 1.f - 2.f * (y * y + z * z);
        Rsm[t][1] = 2.f * (x * y - w * z);
        Rsm[t][2] = 2.f * (x * z + w * y);
        Rsm[t][3] = 2.f * (x * y + w * z);
        Rsm[t][4] = 1.f - 2.f * (x * x + z * z);
        Rsm[t][5] = 2.f * (y * z - w * x);
        Rsm[t][6] = 2.f * (x * z - w * y);
        Rsm[t][7] = 2.f * (y * z + w * x);
        Rsm[t][8] = 1.f - 2.f * (x * x + y * y);
    } else if (t >= 96 && t < 168) {
        int u = t - 96;                        // 0..71
        int j = u / 3, c = u - 3 * j;
        float val = g_JT[j * 33 + 30 + c];
#pragma unroll
        for (int n = 0; n < 10; ++n)
            val += bet[n] * g_JT[j * 33 + n * 3 + c];
        Jm[j][c] = val;
    }
    __syncthreads();

    // A2 row (needs Rsm); 218 threads; does not touch Ag -> overlaps chain
    if (t < 218) {
        float val;
        if (t == 0) val = 1.f;
        else if (t <= 10) val = bet[t - 1];
        else {
            int p = t - 11;
            int i = p / 9 + 1, e = p - 9 * (p / 9);
            val = Rsm[i][e] - ((e == 0 || e == 4 || e == 8) ? 1.f : 0.f);
        }
        g_A2h[(size_t)b * KQ + t] = __float2half_rn(val);
    }

    // Kinematic chain, 9 levels; joints are level-ordered 0..23
    if (t < 12) {
        float val = (t & 3) < 3
            ? Rsm[0][(t >> 2) * 3 + (t & 3)] * ((t & 3) == 0 ? 1.f : -1.f)
            : Jm[0][t >> 2];
        Ag[0][t] = val;
    }
    __syncthreads();
#pragma unroll
    for (int li = 1; li < 9; ++li) {
        const int start = c_lvl[li];
        const int cnt   = c_lvl[li + 1] - start;
        if (t < 12 * cnt) {
            const int i   = start + t / 12;
            const int ln  = t - 12 * (t / 12);
            const int r   = ln >> 2, cc = ln & 3;
            const int par = c_par[i];
            float l0, l1, l2;
            if (cc < 3) {
                l0 = Rsm[i][0 * 3 + cc];
                l1 = Rsm[i][1 * 3 + cc];
                l2 = Rsm[i][2 * 3 + cc];
            } else {
                l0 = Jm[i][0] - Jm[par][0];
                l1 = Jm[i][1] - Jm[par][1];
                l2 = Jm[i][2] - Jm[par][2];
            }
            float val = Ag[par][r * 4 + 0] * l0 + Ag[par][r * 4 + 1] * l1 +
                        Ag[par][r * 4 + 2] * l2;
            if (cc == 3) val += Ag[par][r * 4 + 3];
            Ag[i][r * 4 + cc] = val;
        }
        __syncthreads();
    }

    // Rg: one value per thread (288 values)
    {
        const int j = t / 12, e = t - 12 * j;
        float out;
        if (e < 9) {
            int rr = e / 3, c = e - 3 * rr;
            out = Ag[j][rr * 4 + c];
        } else {
            int rr = e - 9;
            out = Ag[j][rr * 4 + 3] -
                  (Ag[j][rr * 4 + 0] * Jm[j][0] + Ag[j][rr * 4 + 1] * Jm[j][1] +
                   Ag[j][rr * 4 + 2] * Jm[j][2]);
        }
        g_Rg[b * 288 + t] = out;
    }
}

// ---------------------------------------------------------------------------
// GEMM2: P[b][m] = sum_q A2h[b,q]*CTt[m,q], single-term fp16.
// ---------------------------------------------------------------------------
__global__ void __launch_bounds__(256, 2) k_gemm2_wmma() {
    using namespace nvcuda;

    __shared__ __align__(16) __half Ash[128][40];
    __shared__ __align__(16) __half Bs [128][40];

    const int n0  = blockIdx.x * 128;
    const int b0  = blockIdx.y * 128;
    const int tid = threadIdx.x;
    const int wid = tid >> 5;
    const int wb  = (wid & 3) * 32;
    const int wn  = (wid >> 2) * 64;

    wmma::fragment<wmma::accumulator, 16, 16, 16, float> acc[2][4];
#pragma unroll
    for (int i = 0; i < 2; ++i)
#pragma unroll
        for (int j = 0; j < 4; ++j)
            wmma::fill_fragment(acc[i][j], 0.f);

    const int nIter = KQ / 32;                 // 8

    uint4 pA[2], pB[2];
    auto ldg_tile = [&](int kk) {
#pragma unroll
        for (int i = 0; i < 2; ++i) {
            int linear = tid + 256 * i;
            int row = linear >> 2, c = (linear & 3) * 8;
            pA[i] = *(const uint4*)(g_A2h + (size_t)(b0 + row) * KQ + kk + c);
            pB[i] = *(const uint4*)(g_CTt + (size_t)(n0 + row) * KQ + kk + c);
        }
    };

    ldg_tile(0);

    for (int it = 0; it < nIter; ++it) {
        __syncthreads();
#pragma unroll
        for (int i = 0; i < 2; ++i) {
            int linear = tid + 256 * i;
            int row = linear >> 2, c = (linear & 3) * 8;
            *(uint4*)&Ash[row][c] = pA[i];
            *(uint4*)&Bs[row][c]  = pB[i];
        }
        __syncthreads();
        if (it + 1 < nIter) ldg_tile((it + 1) * 32);

#pragma unroll
        for (int k0 = 0; k0 < 32; k0 += 16) {
            wmma::fragment<wmma::matrix_a, 16, 16, 16, __half,
                           wmma::row_major> ah[2];
            wmma::fragment<wmma::matrix_b, 16, 16, 16, __half,
                           wmma::col_major> bh[4];
#pragma unroll
            for (int i = 0; i < 2; ++i)
                wmma::load_matrix_sync(ah[i], &Ash[wb + i * 16][k0], 40);
#pragma unroll
            for (int j = 0; j < 4; ++j)
                wmma::load_matrix_sync(bh[j], &Bs[wn + j * 16][k0], 40);
#pragma unroll
            for (int i = 0; i < 2; ++i)
#pragma unroll
                for (int j = 0; j < 4; ++j)
                    wmma::mma_sync(acc[i][j], ah[i], bh[j], acc[i][j]);
        }
    }

#pragma unroll
    for (int i = 0; i < 2; ++i)
#pragma unroll
        for (int j = 0; j < 4; ++j)
            wmma::store_matrix_sync(
                &g_P[(size_t)(b0 + wb + i * 16) * N2 + n0 + wn + j * 16],
                acc[i][j], N2, wmma::mem_row_major);
}

// ---------------------------------------------------------------------------
// joints epilogue: 4 bodies per CTA (256 threads), sS loaded once per CTA.
// ---------------------------------------------------------------------------
__global__ void __launch_bounds__(256) k_joints(const float* __restrict__ trans,
                                                float* __restrict__ out) {
    const int grp = threadIdx.x >> 6;
    const int t   = threadIdx.x & 63;
    const int b   = blockIdx.x * 4 + grp;

    __shared__ float sA[4][288];
    __shared__ float sS[456];

    for (int i = threadIdx.x; i < 456; i += 256) sS[i] = g_S[i];
    for (int i = t; i < 288; i += 64) sA[grp][i] = g_Rg[b * 288 + i];
    __syncthreads();

    if (t < 57) {
        int k = t / 3, r = t - 3 * k;
        float acc = trans[b * 3 + r];
        const float* Pb = &g_P[(size_t)b * N2];
#pragma unroll
        for (int j = 0; j < 24; ++j) {
            const float* M = &sA[grp][j * 12];
            int m = (k * 24 + j) * 3;
            float p0 = Pb[m + 0], p1 = Pb[m + 1], p2 = Pb[m + 2];
            acc += M[r * 3 + 0] * p0 + M[r * 3 + 1] * p1 + M[r * 3 + 2] * p2 +
                   M[9 + r] * sS[k * 24 + j];
        }
        out[b * 57 + t] = acc;
    }
}

} // namespace smpl

extern "C" void kernel_launch(void* const* d_in, const int* in_sizes, int n_in,
                              void* d_out, int out_size) {
    using namespace smpl;
    const float* beta       = (const float*)d_in[0];
    const float* theta      = (const float*)d_in[1];
    const float* trans      = (const float*)d_in[2];
    const float* v_template = (const float*)d_in[3];
    const float* shapedirs  = (const float*)d_in[4];
    const float* J_reg      = (const float*)d_in[5];
    const float* posedirs   = (const float*)d_in[6];
    const float* joint_reg  = (const float*)d_in[7];
    const float* weights    = (const float*)d_in[8];
    float* out = (float*)d_out;

    cudaFuncSetAttribute(k_gemm1_wmma,
                         cudaFuncAttributeMaxDynamicSharedMemorySize, G1_SMEM);

    // 1) build Eh + Gh (incl. Jreg rows)
    k_build<<<EB + 36, 192>>>(posedirs, shapedirs, v_template,
                              joint_reg, weights, J_reg);

    // 2) GEMM1 fp16 single-term, 128x128, split-K = 6
    {
        dim3 grid(N1 / 128, M1 / 128, SPLITK1);   // 6 x 4 x 6 = 144 CTAs
        k_gemm1_wmma<<<grid, 256, G1_SMEM>>>();
    }

    // 3) reduce partials -> CTt / S / JT
    k_reduce<<<456 * 4 + 24, 128>>>();

    // 4) per-body prep, 1 body per 288-thread CTA, level-parallel chain
    k_prep<<<B, 288>>>(beta, theta);

    // 5) GEMM2 single-term fp16
    {
        dim3 grid(N2 / 128, B / 128);             // 11 x 8
        k_gemm2_wmma<<<grid, 256>>>();
    }

    // 6) joints epilogue, 4 bodies per CTA
    k_joints<<<B / 4, 256>>>(trans, out);
}

// round 15
// speedup vs baseline: 1.3959x; 1.0045x over previous
#include <cuda_runtime.h>
#include <cuda_fp16.h>
#include <mma.h>
#include <cstdint>

// ---------------------------------------------------------------------------
// SMPL fused pipeline, round 15:
//  - reduce+prep fused (prep computes JT from g_Cp itself -> runs concurrently)
//  - build pose path on float2 loads (8B-aligned safe)
//  - 5 launches
// ---------------------------------------------------------------------------

namespace smpl {

constexpr int V    = 6890;
constexpr int NB   = 10;
constexpr int NJ   = 24;
constexpr int NK   = 19;
constexpr int B    = 1024;

constexpr int VP   = 6912;
constexpr int M1   = 512;
constexpr int N1   = 768;
constexpr int SPLITK1 = 6;            // KSEG = 1152
constexpr int KSEG = VP / SPLITK1;
constexpr int KQ   = 256;             // 218 padded
constexpr int N2   = 1408;            // 1368 padded

__device__ __align__(256) __half g_Gh16[M1 * VP];
__device__ __align__(256) __half g_Eh16[N1 * VP];
__device__ __align__(256) __half g_A2h[B * KQ];
__device__ __align__(256) __half g_CTt[N2 * KQ];

__device__ __align__(256) float g_Cp [SPLITK1 * M1 * N1];
__device__ __align__(256) float g_S  [456];
__device__ __align__(256) float g_Rg [B * 288];
__device__ __align__(256) float g_P  [B * N2];

__constant__ int c_par[24] = {-1,0,0,0,1,2,3,4,5,6,7,8,9,9,9,12,13,14,16,17,18,19,20,21};
__constant__ int c_lvl[10] = {0, 1, 4, 7, 10, 15, 18, 20, 22, 24};

// ---------------------------------------------------------------------------
// k_build: Eh rows (241*9 blocks) + Gh rows incl. Jreg (36 blocks).
// ---------------------------------------------------------------------------
constexpr int EB = 241 * 9;           // 2169

__global__ void __launch_bounds__(192) k_build(
        const float* __restrict__ posedirs,
        const float* __restrict__ shapedirs,
        const float* __restrict__ v_template,
        const float* __restrict__ joint_reg,
        const float* __restrict__ weights,
        const float* __restrict__ J_reg) {
    const int b   = blockIdx.x;
    const int tid = threadIdx.x;

    if (b < EB) {
        const int y  = b / 9;
        const int xb = b - 9 * y;
        const int vv = (xb * 192 + tid) * 4;
        if (y < 207) {
            const int p = y;
            const float* src = posedirs + (size_t)p * (V * 3);
            float f[12];
            if (vv + 3 < V) {
                // 12 floats at byte offset 12*vv (vv%4==0 -> 16-aligned within
                // row) + row pitch 82680 (8-aligned) -> float2 always legal.
                const float2* s2 = (const float2*)(src + 3 * vv);
#pragma unroll
                for (int u = 0; u < 6; ++u) {
                    float2 d = s2[u];
                    f[2 * u] = d.x;
                    f[2 * u + 1] = d.y;
                }
            } else {
#pragma unroll
                for (int u = 0; u < 4; ++u)
#pragma unroll
                    for (int c = 0; c < 3; ++c)
                        f[3 * u + c] = (vv + u < V) ? src[3 * (vv + u) + c] : 0.f;
            }
#pragma unroll
            for (int c = 0; c < 3; ++c) {
                __half* dst = g_Eh16 + (size_t)(3 * p + c) * VP + vv;
                *(__half2*)dst       = __floats2half2_rn(f[c], f[3 + c]);
                *(__half2*)(dst + 2) = __floats2half2_rn(f[6 + c], f[9 + c]);
            }
        } else {
            const int n = 621 + (y - 207);     // 621..654
            float f[4] = {0.f, 0.f, 0.f, 0.f};
            if (n < 651) {
                int t = n - 621, q = t / 3, c = t - 3 * q;
                const float* src = shapedirs + (size_t)q * (V * 3);
#pragma unroll
                for (int u = 0; u < 4; ++u)
                    if (vv + u < V) f[u] = src[3 * (vv + u) + c];
            } else if (n < 654) {
                int c = n - 651;
#pragma unroll
                for (int u = 0; u < 4; ++u)
                    if (vv + u < V) f[u] = v_template[3 * (vv + u) + c];
            } else {
#pragma unroll
                for (int u = 0; u < 4; ++u)
                    if (vv + u < V) f[u] = 1.f;
            }
            __half* dst = g_Eh16 + (size_t)n * VP + vv;
            *(__half2*)dst       = __floats2half2_rn(f[0], f[1]);
            *(__half2*)(dst + 2) = __floats2half2_rn(f[2], f[3]);
        }
    } else {
        const int v = (b - EB) * 192 + tid;
        const bool ok = v < V;
        float jr[NK], w[NJ];
#pragma unroll
        for (int c = 0; c < NK; ++c)
            jr[c] = ok ? joint_reg[(size_t)v * NK + c] : 0.f;
#pragma unroll
        for (int c = 0; c < NJ; ++c)
            w[c] = ok ? weights[(size_t)v * NJ + c] : 0.f;
        __half* dst = g_Gh16 + v;
        for (int k = 0; k < NK; ++k) {
            float a = jr[k];
#pragma unroll
            for (int j = 0; j < NJ; ++j)
                dst[(size_t)(k * NJ + j) * VP] = __float2half_rn(a * w[j]);
        }
#pragma unroll
        for (int j = 0; j < NJ; ++j)
            dst[(size_t)(456 + j) * VP] =
                __float2half_rn(ok ? J_reg[(size_t)v * NJ + j] : 0.f);
        // rows 480..511 stay zero (zero-initialized, never written)
    }
}

// ---------------------------------------------------------------------------
// GEMM1: C[m][n] = sum_v Gh[m,v]*Eh[n,v], fp16 single term.
// CTA 128x128, BK=32, 256 threads, 2 CTA/SM, double-buffered 40KB smem.
// ---------------------------------------------------------------------------
constexpr int G1A    = 128 * 40;
constexpr int G1B    = 128 * 40;
constexpr int G1_BUF = G1A + G1B;
constexpr int G1_SMEM = 2 * G1_BUF * 2;        // 40960 bytes

__global__ void __launch_bounds__(256, 2) k_gemm1_wmma() {
    using namespace nvcuda;
    extern __shared__ __align__(16) __half dynsmem[];

    const int n0    = blockIdx.x * 128;
    const int m0    = blockIdx.y * 128;
    const int split = blockIdx.z;
    const int tid   = threadIdx.x;
    const int wid   = tid >> 5;
    const int wm    = (wid & 3) * 32;
    const int wn    = (wid >> 2) * 64;

    wmma::fragment<wmma::accumulator, 16, 16, 16, float> acc[2][4];
#pragma unroll
    for (int i = 0; i < 2; ++i)
#pragma unroll
        for (int j = 0; j < 4; ++j)
            wmma::fill_fragment(acc[i][j], 0.f);

    const int kbase = split * KSEG;
    const int nIter = KSEG / 32;               // 36

    const int r = tid >> 2;
    const int c = (tid & 3) * 8;

    uint4 pA[2], pB[2];

    auto ldg_tile = [&](int kk) {
#pragma unroll
        for (int i = 0; i < 2; ++i) {
            int row = r + 64 * i;
            pA[i] = *(const uint4*)(g_Gh16 + (size_t)(m0 + row) * VP + kk + c);
            pB[i] = *(const uint4*)(g_Eh16 + (size_t)(n0 + row) * VP + kk + c);
        }
    };
    auto sts_tile = [&](int buf) {
        __half* base = dynsmem + buf * G1_BUF;
#pragma unroll
        for (int i = 0; i < 2; ++i) {
            int row = r + 64 * i;
            *(uint4*)(base + row * 40 + c)       = pA[i];
            *(uint4*)(base + G1A + row * 40 + c) = pB[i];
        }
    };

    ldg_tile(kbase);
    sts_tile(0);
    ldg_tile(kbase + 32);
    __syncthreads();

    for (int it = 0; it < nIter; ++it) {
        const int cur = it & 1;
        if (it + 1 < nIter) sts_tile(1 - cur);
        if (it + 2 < nIter) ldg_tile(kbase + (it + 2) * 32);

        const __half* Ah = dynsmem + cur * G1_BUF;
        const __half* Bh = Ah + G1A;
#pragma unroll
        for (int k0 = 0; k0 < 32; k0 += 16) {
            wmma::fragment<wmma::matrix_a, 16, 16, 16, __half,
                           wmma::row_major> ah[2];
            wmma::fragment<wmma::matrix_b, 16, 16, 16, __half,
                           wmma::col_major> bh[4];
#pragma unroll
            for (int i = 0; i < 2; ++i)
                wmma::load_matrix_sync(ah[i], Ah + (wm + i * 16) * 40 + k0, 40);
#pragma unroll
            for (int j = 0; j < 4; ++j)
                wmma::load_matrix_sync(bh[j], Bh + (wn + j * 16) * 40 + k0, 40);
#pragma unroll
            for (int i = 0; i < 2; ++i)
#pragma unroll
                for (int j = 0; j < 4; ++j)
                    wmma::mma_sync(acc[i][j], ah[i], bh[j], acc[i][j]);
        }
        __syncthreads();
    }

    float* Co = g_Cp + (size_t)split * (M1 * N1);
#pragma unroll
    for (int i = 0; i < 2; ++i)
#pragma unroll
        for (int j = 0; j < 4; ++j)
            wmma::store_matrix_sync(
                &Co[(size_t)(m0 + wm + i * 16) * N1 + n0 + wn + j * 16],
                acc[i][j], N1, wmma::mem_row_major);
}

// ---------------------------------------------------------------------------
// Fused reduce + prep. Blocks [0,1024): prep (1 body, JT from g_Cp in smem);
// blocks [1024, 1024+1824): reduce chunks -> CTt/S. 288 threads both.
// ---------------------------------------------------------------------------
__global__ void __launch_bounds__(288) k_redprep(const float* __restrict__ beta,
                                                 const float* __restrict__ theta) {
    const int blk = blockIdx.x;
    const int t   = threadIdx.x;

    if (blk >= B) {
        // ---- reduce part ----
        const int rb    = blk - B;
        const int kj    = rb >> 2;
        const int chunk = rb & 3;
        const int col   = chunk * 164 + t;
        if (t < 164 && col <= 654) {
            float val = 0.f;
            size_t off = (size_t)kj * N1 + col;
#pragma unroll
            for (int sp = 0; sp < SPLITK1; ++sp)
                val += g_Cp[(size_t)sp * (M1 * N1) + off];
            if (col == 654) {
                g_S[kj] = val;
            } else {
                int q, c;
                if (col < 621)      { q = 11 + col / 3; c = col - 3 * (col / 3); }
                else if (col < 651) { int u = col - 621; q = 1 + u / 3; c = u - 3 * (u / 3); }
                else                { q = 0; c = col - 651; }
                g_CTt[(size_t)(3 * kj + c) * KQ + q] = __float2half_rn(val);
            }
        }
        return;
    }

    // ---- prep part: one body ----
    const int b = blk;

    __shared__ float sJT[24 * 33];
    __shared__ float Rsm[24][9];
    __shared__ float Jm[24][3];
    __shared__ float Ag[24][12];
    __shared__ float bet[10];

    if (t < 10) bet[t] = beta[b * NB + t];

    // JT from g_Cp (rows 456..479, cols 621..653): 792 values, 6 planes
    for (int idx = t; idx < 792; idx += 288) {
        int j = idx / 33, tc = idx - 33 * j;
        float val = 0.f;
        size_t off = (size_t)(456 + j) * N1 + 621 + tc;
#pragma unroll
        for (int sp = 0; sp < SPLITK1; ++sp)
            val += g_Cp[(size_t)sp * (M1 * N1) + off];
        sJT[idx] = val;
    }

    if (t < 24) {
        float tx = theta[b * 72 + t * 3 + 0];
        float ty = theta[b * 72 + t * 3 + 1];
        float tz = theta[b * 72 + t * 3 + 2];
        float ax = tx + 1e-8f, ay = ty + 1e-8f, az = tz + 1e-8f;
        float angle = sqrtf(ax * ax + ay * ay + az * az);
        float half = 0.5f * angle;
        float s = sinf(half), cw = cosf(half);
        float vx = tx / angle * s, vy = ty / angle * s, vz = tz / angle * s;
        float qn = sqrtf(cw * cw + vx * vx + vy * vy + vz * vz);
        float w = cw / qn, x = vx / qn, y = vy / qn, z = vz / qn;
        Rsm[t][0] = 1.f - 2.f * (y * y + z * z);
        Rsm[t][1] = 2.f * (x * y - w * z);
        Rsm[t][2] = 2.f * (x * z + w * y);
        Rsm[t][3] = 2.f * (x * y + w * z);
        Rsm[t][4] = 1.f - 2.f * (x * x + z * z);
        Rsm[t][5] = 2.f * (y * z - w * x);
        Rsm[t][6] = 2.f * (x * z - w * y);
        Rsm[t][7] = 2.f * (y * z + w * x);
        Rsm[t][8] = 1.f - 2.f * (x * x + y * y);
    }
    __syncthreads();

    // J regression (72 threads, uses sJT + bet)
    if (t >= 96 && t < 168) {
        int u = t - 96;
        int j = u / 3, c = u - 3 * j;
        float val = sJT[j * 33 + 30 + c];
#pragma unroll
        for (int n = 0; n < 10; ++n)
            val += bet[n] * sJT[j * 33 + n * 3 + c];
        Jm[j][c] = val;
    }

    // A2 row (needs Rsm, bet only)
    if (t < 218) {
        float val;
        if (t == 0) val = 1.f;
        else if (t <= 10) val = bet[t - 1];
        else {
            int p = t - 11;
            int i = p / 9 + 1, e = p - 9 * (p / 9);
            val = Rsm[i][e] - ((e == 0 || e == 4 || e == 8) ? 1.f : 0.f);
        }
        g_A2h[(size_t)b * KQ + t] = __float2half_rn(val);
    }
    __syncthreads();

    // kinematic chain by tree level
    if (t < 12) {
        float val = (t & 3) < 3
            ? Rsm[0][(t >> 2) * 3 + (t & 3)] * ((t & 3) == 0 ? 1.f : -1.f)
            : Jm[0][t >> 2];
        Ag[0][t] = val;
    }
    __syncthreads();
#pragma unroll
    for (int li = 1; li < 9; ++li) {
        const int start = c_lvl[li];
        const int cnt   = c_lvl[li + 1] - start;
        if (t < 12 * cnt) {
            const int i   = start + t / 12;
            const int ln  = t - 12 * (t / 12);
            const int r   = ln >> 2, cc = ln & 3;
            const int par = c_par[i];
            float l0, l1, l2;
            if (cc < 3) {
                l0 = Rsm[i][0 * 3 + cc];
                l1 = Rsm[i][1 * 3 + cc];
                l2 = Rsm[i][2 * 3 + cc];
            } else {
                l0 = Jm[i][0] - Jm[par][0];
                l1 = Jm[i][1] - Jm[par][1];
                l2 = Jm[i][2] - Jm[par][2];
            }
            float val = Ag[par][r * 4 + 0] * l0 + Ag[par][r * 4 + 1] * l1 +
                        Ag[par][r * 4 + 2] * l2;
            if (cc == 3) val += Ag[par][r * 4 + 3];
            Ag[i][r * 4 + cc] = val;
        }
        __syncthreads();
    }

    // Rg: one value per thread
    {
        const int j = t / 12, e = t - 12 * j;
        float out;
        if (e < 9) {
            int rr = e / 3, c = e - 3 * rr;
            out = Ag[j][rr * 4 + c];
        } else {
            int rr = e - 9;
            out = Ag[j][rr * 4 + 3] -
                  (Ag[j][rr * 4 + 0] * Jm[j][0] + Ag[j][rr * 4 + 1] * Jm[j][1] +
                   Ag[j][rr * 4 + 2] * Jm[j][2]);
        }
        g_Rg[b * 288 + t] = out;
    }
}

// ---------------------------------------------------------------------------
// GEMM2: P[b][m] = sum_q A2h[b,q]*CTt[m,q], single-term fp16.
// ---------------------------------------------------------------------------
__global__ void __launch_bounds__(256, 2) k_gemm2_wmma() {
    using namespace nvcuda;

    __shared__ __align__(16) __half Ash[128][40];
    __shared__ __align__(16) __half Bs [128][40];

    const int n0  = blockIdx.x * 128;
    const int b0  = blockIdx.y * 128;
    const int tid = threadIdx.x;
    const int wid = tid >> 5;
    const int wb  = (wid & 3) * 32;
    const int wn  = (wid >> 2) * 64;

    wmma::fragment<wmma::accumulator, 16, 16, 16, float> acc[2][4];
#pragma unroll
    for (int i = 0; i < 2; ++i)
#pragma unroll
        for (int j = 0; j < 4; ++j)
            wmma::fill_fragment(acc[i][j], 0.f);

    const int nIter = KQ / 32;                 // 8

    uint4 pA[2], pB[2];
    auto ldg_tile = [&](int kk) {
#pragma unroll
        for (int i = 0; i < 2; ++i) {
            int linear = tid + 256 * i;
            int row = linear >> 2, c = (linear & 3) * 8;
            pA[i] = *(const uint4*)(g_A2h + (size_t)(b0 + row) * KQ + kk + c);
            pB[i] = *(const uint4*)(g_CTt + (size_t)(n0 + row) * KQ + kk + c);
        }
    };

    ldg_tile(0);

    for (int it = 0; it < nIter; ++it) {
        __syncthreads();
#pragma unroll
        for (int i = 0; i < 2; ++i) {
            int linear = tid + 256 * i;
            int row = linear >> 2, c = (linear & 3) * 8;
            *(uint4*)&Ash[row][c] = pA[i];
            *(uint4*)&Bs[row][c]  = pB[i];
        }
        __syncthreads();
        if (it + 1 < nIter) ldg_tile((it + 1) * 32);

#pragma unroll
        for (int k0 = 0; k0 < 32; k0 += 16) {
            wmma::fragment<wmma::matrix_a, 16, 16, 16, __half,
                           wmma::row_major> ah[2];
            wmma::fragment<wmma::matrix_b, 16, 16, 16, __half,
                           wmma::col_major> bh[4];
#pragma unroll
            for (int i = 0; i < 2; ++i)
                wmma::load_matrix_sync(ah[i], &Ash[wb + i * 16][k0], 40);
#pragma unroll
            for (int j = 0; j < 4; ++j)
                wmma::load_matrix_sync(bh[j], &Bs[wn + j * 16][k0], 40);
#pragma unroll
            for (int i = 0; i < 2; ++i)
#pragma unroll
                for (int j = 0; j < 4; ++j)
                    wmma::mma_sync(acc[i][j], ah[i], bh[j], acc[i][j]);
        }
    }

#pragma unroll
    for (int i = 0; i < 2; ++i)
#pragma unroll
        for (int j = 0; j < 4; ++j)
            wmma::store_matrix_sync(
                &g_P[(size_t)(b0 + wb + i * 16) * N2 + n0 + wn + j * 16],
                acc[i][j], N2, wmma::mem_row_major);
}

// ---------------------------------------------------------------------------
// joints epilogue: 4 bodies per CTA.
// ---------------------------------------------------------------------------
__global__ void __launch_bounds__(256) k_joints(const float* __restrict__ trans,
                                                float* __restrict__ out) {
    const int grp = threadIdx.x >> 6;
    const int t   = threadIdx.x & 63;
    const int b   = blockIdx.x * 4 + grp;

    __shared__ float sA[4][288];
    __shared__ float sS[456];

    for (int i = threadIdx.x; i < 456; i += 256) sS[i] = g_S[i];
    for (int i = t; i < 288; i += 64) sA[grp][i] = g_Rg[b * 288 + i];
    __syncthreads();

    if (t < 57) {
        int k = t / 3, r = t - 3 * k;
        float acc = trans[b * 3 + r];
        const float* Pb = &g_P[(size_t)b * N2];
#pragma unroll
        for (int j = 0; j < 24; ++j) {
            const float* M = &sA[grp][j * 12];
            int m = (k * 24 + j) * 3;
            float p0 = Pb[m + 0], p1 = Pb[m + 1], p2 = Pb[m + 2];
            acc += M[r * 3 + 0] * p0 + M[r * 3 + 1] * p1 + M[r * 3 + 2] * p2 +
                   M[9 + r] * sS[k * 24 + j];
        }
        out[b * 57 + t] = acc;
    }
}

} // namespace smpl

extern "C" void kernel_launch(void* const* d_in, const int* in_sizes, int n_in,
                              void* d_out, int out_size) {
    using namespace smpl;
    const float* beta       = (const float*)d_in[0];
    const float* theta      = (const float*)d_in[1];
    const float* trans      = (const float*)d_in[2];
    const float* v_template = (const float*)d_in[3];
    const float* shapedirs  = (const float*)d_in[4];
    const float* J_reg      = (const float*)d_in[5];
    const float* posedirs   = (const float*)d_in[6];
    const float* joint_reg  = (const float*)d_in[7];
    const float* weights    = (const float*)d_in[8];
    float* out = (float*)d_out;

    cudaFuncSetAttribute(k_gemm1_wmma,
                         cudaFuncAttributeMaxDynamicSharedMemorySize, G1_SMEM);

    // 1) build Eh + Gh
    k_build<<<EB + 36, 192>>>(posedirs, shapedirs, v_template,
                              joint_reg, weights, J_reg);

    // 2) GEMM1 fp16 single-term, 128x128, split-K = 6
    {
        dim3 grid(N1 / 128, M1 / 128, SPLITK1);   // 6 x 4 x 6 = 144 CTAs
        k_gemm1_wmma<<<grid, 256, G1_SMEM>>>();
    }

    // 3) fused reduce + prep (prep blocks first)
    k_redprep<<<B + 456 * 4, 288>>>(beta, theta);

    // 4) GEMM2 single-term fp16
    {
        dim3 grid(N2 / 128, B / 128);             // 11 x 8
        k_gemm2_wmma<<<grid, 256>>>();
    }

    // 5) joints epilogue
    k_joints<<<B / 4, 256>>>(trans, out);
}